// round 12
// baseline (speedup 1.0000x reference)
#include <cuda_runtime.h>
#include <cuda_bf16.h>
#include <math.h>

#define NN   50000
#define EE   800000
#define DIN  128
#define HH   256
#define CC   47
#define CP   48
#define CPZ  64    // padded bf16 z row (128 B)
#define NB   ((NN + 255) / 256)   // 196 scan blocks

// ---------------- scratch (device globals) -----------------------------------
__device__ __nv_bfloat16 g_xh  [(size_t)NN * DIN];
__device__ __nv_bfloat16 g_aggb[(size_t)NN * DIN];
__device__ __nv_bfloat16 g_h1b [(size_t)NN * HH];
__device__ __nv_bfloat16 g_w1t [256 * HH];           // [n=256][k=256]
__device__ __nv_bfloat16 g_w2t [96 * HH];            // [n=96][k=256]
__device__ __nv_bfloat16 g_zb  [(size_t)NN * CPZ];   // cols 48-63 stay 0
__device__ float g_s   [(size_t)NN * CP];
__device__ int   g_rp  [NN];
__device__ int   g_bsum[256];
__device__ int   g_adj [EE];
__device__ int   g_slot[EE];
// g_meta: [0,NN)=deg, [NN+0]=bytemask, [NN+1]=scan done,
//         [NN+2..3]=loss acc (f32 bits), [NN+4]=loss blocksDone
__device__ int   g_meta[NN + 8];

__device__ __forceinline__ void mma_bf16(float c[4],
        unsigned a0, unsigned a1, unsigned a2, unsigned a3,
        unsigned b0, unsigned b1) {
    asm volatile("mma.sync.aligned.m16n8k16.row.col.f32.bf16.bf16.f32 "
                 "{%0,%1,%2,%3},{%4,%5,%6,%7},{%8,%9},{%0,%1,%2,%3};"
                 : "+f"(c[0]), "+f"(c[1]), "+f"(c[2]), "+f"(c[3])
                 : "r"(a0), "r"(a1), "r"(a2), "r"(a3), "r"(b0), "r"(b1));
}
__device__ __forceinline__ void ldsm4(unsigned &r0, unsigned &r1, unsigned &r2, unsigned &r3,
                                      const void* p) {
    unsigned a = (unsigned)__cvta_generic_to_shared(p);
    asm volatile("ldmatrix.sync.aligned.m8n8.x4.shared.b16 {%0,%1,%2,%3}, [%4];"
                 : "=r"(r0), "=r"(r1), "=r"(r2), "=r"(r3) : "r"(a));
}
__device__ __forceinline__ void ldsm2(unsigned &r0, unsigned &r1, const void* p) {
    unsigned a = (unsigned)__cvta_generic_to_shared(p);
    asm volatile("ldmatrix.sync.aligned.m8n8.x2.shared.b16 {%0,%1}, [%2];"
                 : "=r"(r0), "=r"(r1) : "r"(a));
}
__device__ __forceinline__ void cpa16(void* dst, const void* src, bool p) {
    unsigned d = (unsigned)__cvta_generic_to_shared(dst);
    int sz = p ? 16 : 0;
    asm volatile("cp.async.ca.shared.global [%0], [%1], 16, %2;"
                 :: "r"(d), "l"(src), "r"(sz) : "memory");
}
__device__ __forceinline__ unsigned bf2pack(float lo, float hi) {
    unsigned r;
    asm("cvt.rn.bf16x2.f32 %0, %1, %2;" : "=r"(r) : "f"(hi), "f"(lo));
    return r;
}
__device__ __forceinline__ unsigned long long bfup(unsigned w) {
    unsigned long long p;
    unsigned lo = w << 16, hi = w & 0xffff0000u;
    asm("mov.b64 %0, {%1, %2};" : "=l"(p) : "r"(lo), "r"(hi));
    return p;
}
__device__ __forceinline__ unsigned long long addx2(unsigned long long a, unsigned long long b) {
    unsigned long long r;
    asm("add.rn.f32x2 %0, %1, %2;" : "=l"(r) : "l"(a), "l"(b));
    return r;
}
__device__ __forceinline__ void unpx2(float &lo, float &hi, unsigned long long p) {
    asm("mov.b64 {%0, %1}, %2;" : "=f"(lo), "=f"(hi) : "l"(p));
}

// ---------------- K1: block-range front (x pack | deg+slot+mask | w pack) ----
#define FB_X 1024
#define FB_E 768
#define FB_W 256
#define PREP_W1 (256 * HH)
#define PREP_W2 (96 * HH)
__global__ void k_front(const int* __restrict__ row,
                        const unsigned int* __restrict__ mw,
                        const float* __restrict__ x,
                        const float* __restrict__ w1n, const float* __restrict__ w1s,
                        const float* __restrict__ w2n, const float* __restrict__ w2s) {
    int b = blockIdx.x, t = threadIdx.x;
    if (b < FB_X) {
        int stride = FB_X * 256;
        const float4* xs = reinterpret_cast<const float4*>(x);
        for (int i = b * 256 + t; i < NN * DIN / 4; i += stride) {
            float4 v = xs[i];
            uint2 r;
            r.x = bf2pack(v.x, v.y);
            r.y = bf2pack(v.z, v.w);
            reinterpret_cast<uint2*>(g_xh)[i] = r;
        }
    } else if (b < FB_X + FB_E) {
        int i0 = (b - FB_X) * 256 + t, stride = FB_E * 256;
        for (int i = i0; i < EE; i += stride)
            g_slot[i] = atomicAdd(&g_meta[row[i]], 1);
        for (int i = i0; i < NN / 4; i += stride)
            if (mw[i] > 1u) g_meta[NN] = 1;
    } else {
        int i0 = (b - FB_X - FB_E) * 256 + t, stride = FB_W * 256;
        for (int i = i0; i < PREP_W1 + PREP_W2; i += stride) {
            if (i < PREP_W1) {
                int n = i >> 8, k = i & 255;
                float v = (k < DIN) ? w1n[k * HH + n] : w1s[(k - DIN) * HH + n];
                g_w1t[i] = __float2bfloat16(v);
            } else {
                int j = i - PREP_W1;
                int n = j >> 8, k = j & 255;
                float v = 0.f;
                if (n < CP) { if (n < CC) v = w2n[k * CC + n]; }
                else        { int n2 = n - CP; if (n2 < CC) v = w2s[k * CC + n2]; }
                g_w2t[j] = __float2bfloat16(v);
            }
        }
    }
}

// ---------------- K2: block scan + last-block finalize -----------------------
__global__ void k_scan() {
    __shared__ int sh[256];
    __shared__ int islast;
    int i = blockIdx.x * 256 + threadIdx.x;
    int v = (i < NN) ? g_meta[i] : 0;
    sh[threadIdx.x] = v;
    __syncthreads();
    for (int o = 1; o < 256; o <<= 1) {
        int t = (threadIdx.x >= o) ? sh[threadIdx.x - o] : 0;
        __syncthreads();
        sh[threadIdx.x] += t;
        __syncthreads();
    }
    int incl = sh[threadIdx.x];
    if (i < NN) g_rp[i] = incl - v;
    if (threadIdx.x == 255) g_bsum[blockIdx.x] = incl;

    __threadfence();
    if (threadIdx.x == 0) {
        int old = atomicAdd(&g_meta[NN + 1], 1);
        islast = (old == gridDim.x - 1);
    }
    __syncthreads();
    if (islast) {
        int b = threadIdx.x;
        int bv = (b < NB) ? g_bsum[b] : 0;
        sh[b] = bv;
        __syncthreads();
        for (int o = 1; o < 256; o <<= 1) {
            int t = (b >= o) ? sh[b - o] : 0;
            __syncthreads();
            sh[b] += t;
            __syncthreads();
        }
        if (b < NB) g_bsum[b] = sh[b] - bv;
    }
}

// ---------------- K3: fill adjacency (atomic-free) ---------------------------
__global__ void k_fill(const int* __restrict__ row, const int* __restrict__ col) {
    int e = blockIdx.x * blockDim.x + threadIdx.x;
    if (e >= EE) return;
    int r = row[e];
    g_adj[g_rp[r] + g_bsum[r >> 8] + g_slot[e]] = col[e];
}

// ---------------- K4: agg1 — 2 warps per node, smem combine ------------------
// 512 threads = 8 nodes/block. Warp pair (half=0/1) splits edges; each warp
// runs the lean R8 inner loop (2 edges in flight, regs stay ~32).
__global__ __launch_bounds__(512) void k_agg1() {
    __shared__ unsigned long long sred[8][16][4];
    int tid = threadIdx.x;
    int gw = (blockIdx.x * 512 + tid) >> 6;     // node id (64 threads per node)
    int nl = tid >> 6;                          // node-local 0..7
    int half = (tid >> 5) & 1;
    int lane = tid & 31;
    int e = lane >> 4, c = lane & 15;
    unsigned long long acc0 = 0, acc1 = 0, acc2 = 0, acc3 = 0;
    int d = 0;
    if (gw < NN) {
        d = g_meta[gw];
        int start = g_rp[gw] + g_bsum[gw >> 8];
        for (int j = half * 2; j < d; j += 4) {
            int jj = j + e;
            if (jj < d) {
                int s = g_adj[start + jj];
                uint4 v = reinterpret_cast<const uint4*>(g_xh + (size_t)s * DIN)[c];
                acc0 = addx2(acc0, bfup(v.x));
                acc1 = addx2(acc1, bfup(v.y));
                acc2 = addx2(acc2, bfup(v.z));
                acc3 = addx2(acc3, bfup(v.w));
            }
        }
        acc0 = addx2(acc0, __shfl_xor_sync(0xffffffffu, acc0, 16));
        acc1 = addx2(acc1, __shfl_xor_sync(0xffffffffu, acc1, 16));
        acc2 = addx2(acc2, __shfl_xor_sync(0xffffffffu, acc2, 16));
        acc3 = addx2(acc3, __shfl_xor_sync(0xffffffffu, acc3, 16));
        if (half == 1 && e == 0) {
            sred[nl][c][0] = acc0;
            sred[nl][c][1] = acc1;
            sred[nl][c][2] = acc2;
            sred[nl][c][3] = acc3;
        }
    }
    __syncthreads();
    if (gw < NN && half == 0 && e == 0) {
        acc0 = addx2(acc0, sred[nl][c][0]);
        acc1 = addx2(acc1, sred[nl][c][1]);
        acc2 = addx2(acc2, sred[nl][c][2]);
        acc3 = addx2(acc3, sred[nl][c][3]);
        float inv = d > 0 ? 1.0f / (float)d : 0.f;
        float lo, hi;
        uint4 r;
        unpx2(lo, hi, acc0); r.x = bf2pack(lo * inv, hi * inv);
        unpx2(lo, hi, acc1); r.y = bf2pack(lo * inv, hi * inv);
        unpx2(lo, hi, acc2); r.z = bf2pack(lo * inv, hi * inv);
        unpx2(lo, hi, acc3); r.w = bf2pack(lo * inv, hi * inv);
        reinterpret_cast<uint4*>(g_aggb + (size_t)gw * DIN)[c] = r;
    }
}

// ---------------- GEMM1 (bf16 mma, 3-stage): h1 = relu([aggb|xh]@w1t^T + b) --
#define G1_SMEM (3*128*72*2 + 3*128*72*2 + 128*4)
__global__ __launch_bounds__(256) void k_gemm1(
        const float* __restrict__ b1n, const float* __restrict__ b1s) {
    extern __shared__ __nv_bfloat16 sm[];
    __nv_bfloat16* As = sm;
    __nv_bfloat16* Bs = sm + 3 * 128 * 72;
    float* sbias = reinterpret_cast<float*>(Bs + 3 * 128 * 72);

    int tid  = threadIdx.x;
    int row0 = blockIdx.y * 128;
    int col0 = blockIdx.x * 128;
    if (tid < 128) sbias[tid] = b1n[col0 + tid] + b1s[col0 + tid];

    int lane = tid & 31, wid = tid >> 5;
    int m_w = (wid & 1) * 64;
    int n_w = (wid >> 1) * 32;

#define AS1(s,m,k) (As + ((s)*128 + (m))*72 + (k))
#define BS1(s,n,k) (Bs + ((s)*128 + (n))*72 + (k))

    auto load_tiles = [&](int s, int kt) {
        #pragma unroll
        for (int i = 0; i < 4; ++i) {
            int idx = tid + i * 256;
            int r = idx >> 3, c = (idx & 7) * 8;
            int gm = row0 + r;
            bool p = gm < NN;
            int gmc = p ? gm : 0;
            const __nv_bfloat16* src = (kt < 2)
                ? g_aggb + (size_t)gmc * DIN + kt * 64 + c
                : g_xh   + (size_t)gmc * DIN + (kt - 2) * 64 + c;
            cpa16(AS1(s, r, c), src, p);
        }
        #pragma unroll
        for (int i = 0; i < 4; ++i) {
            int idx = tid + i * 256;
            int r = idx >> 3, c = (idx & 7) * 8;
            cpa16(BS1(s, r, c), g_w1t + (size_t)(col0 + r) * 256 + kt * 64 + c, true);
        }
    };

    float acc[4][4][4] = {};
    load_tiles(0, 0);
    asm volatile("cp.async.commit_group;" ::: "memory");
    load_tiles(1, 1);
    asm volatile("cp.async.commit_group;" ::: "memory");

    for (int kt = 0; kt < 4; ++kt) {
        if (kt + 2 < 4) load_tiles((kt + 2) % 3, kt + 2);
        asm volatile("cp.async.commit_group;" ::: "memory");
        asm volatile("cp.async.wait_group 2;" ::: "memory");
        __syncthreads();
        int buf = kt % 3;
        #pragma unroll
        for (int ks = 0; ks < 4; ++ks) {
            int kk = ks * 16;
            unsigned af[4][4];
            #pragma unroll
            for (int mt = 0; mt < 4; ++mt) {
                int m = m_w + mt * 16 + (lane & 15);
                int c = kk + (lane >> 4) * 8;
                ldsm4(af[mt][0], af[mt][1], af[mt][2], af[mt][3], AS1(buf, m, c));
            }
            unsigned bf[4][2];
            #pragma unroll
            for (int nt = 0; nt < 4; ++nt) {
                int n = n_w + nt * 8 + (lane & 7);
                int c = kk + ((lane >> 3) & 1) * 8;
                ldsm2(bf[nt][0], bf[nt][1], BS1(buf, n, c));
            }
            #pragma unroll
            for (int mt = 0; mt < 4; ++mt)
                #pragma unroll
                for (int nt = 0; nt < 4; ++nt)
                    mma_bf16(acc[mt][nt], af[mt][0], af[mt][1], af[mt][2], af[mt][3],
                             bf[nt][0], bf[nt][1]);
        }
        __syncthreads();
    }

    int g = lane >> 2, tg = lane & 3;
    #pragma unroll
    for (int mt = 0; mt < 4; ++mt) {
        int mb = row0 + m_w + mt * 16 + g;
        #pragma unroll
        for (int nt = 0; nt < 4; ++nt) {
            int nl = n_w + nt * 8 + 2 * tg;
            int gn = col0 + nl;
            float b0 = sbias[nl], b1 = sbias[nl + 1];
            if (mb < NN) {
                unsigned r = bf2pack(fmaxf(acc[mt][nt][0] + b0, 0.f),
                                     fmaxf(acc[mt][nt][1] + b1, 0.f));
                *reinterpret_cast<unsigned*>(g_h1b + (size_t)mb * HH + gn) = r;
            }
            if (mb + 8 < NN) {
                unsigned r = bf2pack(fmaxf(acc[mt][nt][2] + b0, 0.f),
                                     fmaxf(acc[mt][nt][3] + b1, 0.f));
                *reinterpret_cast<unsigned*>(g_h1b + (size_t)(mb + 8) * HH + gn) = r;
            }
        }
    }
}

// ---------------- GEMM2 (bf16 mma): [z|s] = h1b @ w2t^T ----------------------
#define G2_SMEM (2*128*72*2 + 2*96*72*2)
__global__ __launch_bounds__(256) void k_gemm2() {
    extern __shared__ __nv_bfloat16 sm[];
    __nv_bfloat16* As = sm;
    __nv_bfloat16* Bs = sm + 2 * 128 * 72;

    int tid  = threadIdx.x;
    int row0 = blockIdx.y * 128;
    int lane = tid & 31, wid = tid >> 5;
    int m_w = (wid & 3) * 32;
    int n_w = (wid >> 2) * 48;

#define AS2(s,m,k) (As + ((s)*128 + (m))*72 + (k))
#define BS2(s,n,k) (Bs + ((s)*96 + (n))*72 + (k))

    auto load_tiles = [&](int s, int kt) {
        #pragma unroll
        for (int i = 0; i < 4; ++i) {
            int idx = tid + i * 256;
            int r = idx >> 3, c = (idx & 7) * 8;
            int gm = row0 + r;
            bool p = gm < NN;
            int gmc = p ? gm : 0;
            cpa16(AS2(s, r, c), g_h1b + (size_t)gmc * HH + kt * 64 + c, p);
        }
        #pragma unroll
        for (int i = 0; i < 3; ++i) {
            int idx = tid + i * 256;
            int r = idx >> 3, c = (idx & 7) * 8;
            cpa16(BS2(s, r, c), g_w2t + (size_t)r * 256 + kt * 64 + c, true);
        }
    };

    float acc[2][6][4] = {};
    load_tiles(0, 0);
    asm volatile("cp.async.commit_group;" ::: "memory");

    for (int kt = 0; kt < 4; ++kt) {
        if (kt + 1 < 4) {
            load_tiles((kt + 1) & 1, kt + 1);
            asm volatile("cp.async.commit_group;" ::: "memory");
            asm volatile("cp.async.wait_group 1;" ::: "memory");
        } else {
            asm volatile("cp.async.wait_group 0;" ::: "memory");
        }
        __syncthreads();
        int buf = kt & 1;
        #pragma unroll
        for (int ks = 0; ks < 4; ++ks) {
            int kk = ks * 16;
            unsigned af[2][4];
            #pragma unroll
            for (int mt = 0; mt < 2; ++mt) {
                int m = m_w + mt * 16 + (lane & 15);
                int c = kk + (lane >> 4) * 8;
                ldsm4(af[mt][0], af[mt][1], af[mt][2], af[mt][3], AS2(buf, m, c));
            }
            unsigned bf[6][2];
            #pragma unroll
            for (int nt = 0; nt < 6; ++nt) {
                int n = n_w + nt * 8 + (lane & 7);
                int c = kk + ((lane >> 3) & 1) * 8;
                ldsm2(bf[nt][0], bf[nt][1], BS2(buf, n, c));
            }
            #pragma unroll
            for (int mt = 0; mt < 2; ++mt)
                #pragma unroll
                for (int nt = 0; nt < 6; ++nt)
                    mma_bf16(acc[mt][nt], af[mt][0], af[mt][1], af[mt][2], af[mt][3],
                             bf[nt][0], bf[nt][1]);
        }
        __syncthreads();
    }

    int g = lane >> 2, tg = lane & 3;
    #pragma unroll
    for (int mt = 0; mt < 2; ++mt) {
        int mb = row0 + m_w + mt * 16 + g;
        #pragma unroll
        for (int nt = 0; nt < 6; ++nt) {
            int n = n_w + nt * 8 + 2 * tg;
            if (n < CP) {
                if (mb < NN)
                    *reinterpret_cast<unsigned*>(g_zb + (size_t)mb * CPZ + n) =
                        bf2pack(acc[mt][nt][0], acc[mt][nt][1]);
                if (mb + 8 < NN)
                    *reinterpret_cast<unsigned*>(g_zb + (size_t)(mb + 8) * CPZ + n) =
                        bf2pack(acc[mt][nt][2], acc[mt][nt][3]);
            } else {
                int n2 = n - CP;
                if (mb < NN)
                    *reinterpret_cast<float2*>(g_s + (size_t)mb * CP + n2) =
                        make_float2(acc[mt][nt][0], acc[mt][nt][1]);
                if (mb + 8 < NN)
                    *reinterpret_cast<float2*>(g_s + (size_t)(mb + 8) * CP + n2) =
                        make_float2(acc[mt][nt][2], acc[mt][nt][3]);
            }
        }
    }
}

// ---------------- fused agg2 + loss + finalize (R9 form) ---------------------
__global__ void k_loss(const int* __restrict__ y,
                       const void* __restrict__ maskp,
                       const float* __restrict__ b2n,
                       const float* __restrict__ b2s,
                       float* __restrict__ out) {
    __shared__ float sz[8][64];
    __shared__ int islast;
    int w = (blockIdx.x * blockDim.x + threadIdx.x) >> 5;
    int lane = threadIdx.x & 31;
    int wl = (threadIdx.x >> 5) & 7;

    if (w < NN) {
        int d = g_meta[w];
        int start = g_rp[w] + g_bsum[w >> 8];
        int e = lane >> 3, c = lane & 7;
        unsigned long long acc0 = 0, acc1 = 0, acc2 = 0, acc3 = 0;
        for (int j = 0; j < d; j += 4) {
            int jj = j + e;
            if (jj < d) {
                int s = g_adj[start + jj];
                uint4 v = reinterpret_cast<const uint4*>(g_zb + (size_t)s * CPZ)[c];
                acc0 = addx2(acc0, bfup(v.x));
                acc1 = addx2(acc1, bfup(v.y));
                acc2 = addx2(acc2, bfup(v.z));
                acc3 = addx2(acc3, bfup(v.w));
            }
        }
        acc0 = addx2(acc0, __shfl_xor_sync(0xffffffffu, acc0, 8));
        acc1 = addx2(acc1, __shfl_xor_sync(0xffffffffu, acc1, 8));
        acc2 = addx2(acc2, __shfl_xor_sync(0xffffffffu, acc2, 8));
        acc3 = addx2(acc3, __shfl_xor_sync(0xffffffffu, acc3, 8));
        acc0 = addx2(acc0, __shfl_xor_sync(0xffffffffu, acc0, 16));
        acc1 = addx2(acc1, __shfl_xor_sync(0xffffffffu, acc1, 16));
        acc2 = addx2(acc2, __shfl_xor_sync(0xffffffffu, acc2, 16));
        acc3 = addx2(acc3, __shfl_xor_sync(0xffffffffu, acc3, 16));
        if (e == 0) {
            float inv = d > 0 ? 1.0f / (float)d : 0.f;
            float lo, hi;
            unpx2(lo, hi, acc0); sz[wl][c * 8 + 0] = lo * inv; sz[wl][c * 8 + 1] = hi * inv;
            unpx2(lo, hi, acc1); sz[wl][c * 8 + 2] = lo * inv; sz[wl][c * 8 + 3] = hi * inv;
            unpx2(lo, hi, acc2); sz[wl][c * 8 + 4] = lo * inv; sz[wl][c * 8 + 5] = hi * inv;
            unpx2(lo, hi, acc3); sz[wl][c * 8 + 6] = lo * inv; sz[wl][c * 8 + 7] = hi * inv;
        }
        __syncwarp();

        const float* ss = g_s + (size_t)w * CP;
        int j2 = lane + 32;
        float l1 = sz[wl][lane] + ss[lane] + b2n[lane] + b2s[lane];
        float l2 = -1e30f;
        if (j2 < CC) l2 = sz[wl][j2] + ss[j2] + b2n[j2] + b2s[j2];

        float m = fmaxf(l1, l2);
        #pragma unroll
        for (int o = 16; o; o >>= 1) m = fmaxf(m, __shfl_xor_sync(0xffffffffu, m, o));
        float se = expf(l1 - m) + ((j2 < CC) ? expf(l2 - m) : 0.f);
        #pragma unroll
        for (int o = 16; o; o >>= 1) se += __shfl_xor_sync(0xffffffffu, se, o);

        if (lane == 0) {
            bool bytemode = (g_meta[NN] != 0);
            bool tm = bytemode ? (((const unsigned char*)maskp)[w] != 0)
                               : (((const int*)maskp)[w] != 0);
            if (tm) {
                int yy = y[w];
                float ly = sz[wl][yy] + ss[yy] + b2n[yy] + b2s[yy];
                float nll = m + logf(se) - ly;
                atomicAdd(reinterpret_cast<float*>(&g_meta[NN + 2]), nll);
                atomicAdd(reinterpret_cast<float*>(&g_meta[NN + 3]), 1.0f);
            }
        }
    }

    __threadfence();
    __syncthreads();
    if (threadIdx.x == 0) {
        int old = atomicAdd(&g_meta[NN + 4], 1);
        islast = (old == gridDim.x - 1);
    }
    __syncthreads();
    if (islast && threadIdx.x == 0) {
        float a = __int_as_float(g_meta[NN + 2]);
        float c = __int_as_float(g_meta[NN + 3]);
        out[0] = a / fmaxf(c, 1.0f);
    }
}

// ---------------- host launcher ----------------------------------------------
extern "C" void kernel_launch(void* const* d_in, const int* in_sizes, int n_in,
                              void* d_out, int out_size) {
    const float* x    = (const float*)d_in[0];
    const int*   row  = (const int*)d_in[1];
    const int*   col  = (const int*)d_in[2];
    const int*   y    = (const int*)d_in[3];
    const void*  mask = d_in[4];
    const float* w1n = (const float*)d_in[5];
    const float* b1n = (const float*)d_in[6];
    const float* w1s = (const float*)d_in[7];
    const float* b1s = (const float*)d_in[8];
    const float* w2n = (const float*)d_in[9];
    const float* b2n = (const float*)d_in[10];
    const float* w2s = (const float*)d_in[11];
    const float* b2s = (const float*)d_in[12];
    float* out = (float*)d_out;

    static int cfg = 0;
    if (!cfg) {
        cudaFuncSetAttribute(k_gemm1, cudaFuncAttributeMaxDynamicSharedMemorySize, G1_SMEM);
        cudaFuncSetAttribute(k_gemm2, cudaFuncAttributeMaxDynamicSharedMemorySize, G2_SMEM);
        cfg = 1;
    }

    void* p_meta;
    cudaGetSymbolAddress(&p_meta, g_meta);
    cudaMemsetAsync(p_meta, 0, (NN + 8) * sizeof(int));

    k_front<<<FB_X + FB_E + FB_W, 256>>>(row, (const unsigned int*)mask, x,
                                         w1n, w1s, w2n, w2s);
    k_scan<<<NB, 256>>>();
    k_fill<<<(EE + 255) / 256, 256>>>(row, col);
    k_agg1<<<(NN * 64 + 511) / 512, 512>>>();
    {
        dim3 grid(HH / 128, (NN + 127) / 128);
        k_gemm1<<<grid, 256, G1_SMEM>>>(b1n, b1s);
    }
    {
        dim3 grid(1, (NN + 127) / 128);
        k_gemm2<<<grid, 256, G2_SMEM>>>();
    }
    k_loss<<<(NN * 32 + 255) / 256, 256>>>(y, mask, b2n, b2s, out);
}

// round 13
// speedup vs baseline: 1.0427x; 1.0427x over previous
#include <cuda_runtime.h>
#include <cuda_bf16.h>
#include <math.h>

#define NN   50000
#define EE   800000
#define DIN  128
#define HH   256
#define CC   47
#define CP   48
#define CPZ  64    // padded bf16 z row (128 B)
#define NB   ((NN + 255) / 256)   // 196 scan blocks

// ---------------- scratch (device globals) -----------------------------------
__device__ __nv_bfloat16 g_xh  [(size_t)NN * DIN];
__device__ __nv_bfloat16 g_aggb[(size_t)NN * DIN];
__device__ __nv_bfloat16 g_h1b [(size_t)NN * HH];
__device__ __nv_bfloat16 g_w1t [256 * HH];           // [n=256][k=256]
__device__ __nv_bfloat16 g_w2t [96 * HH];            // [n=96][k=256]
__device__ __nv_bfloat16 g_zb  [(size_t)NN * CPZ];   // cols 48-63 stay 0
__device__ float g_s   [(size_t)NN * CP];
__device__ int   g_rp  [NN];
__device__ int   g_bsum[256];
__device__ int   g_adj [EE];
__device__ int   g_slot[EE];                         // per-edge slot within its node
// g_meta: [0,NN)=deg, [NN+0]=bytemask, [NN+1]=scan done,
//         [NN+2..3]=loss acc (f32 bits), [NN+4]=loss blocksDone
__device__ int   g_meta[NN + 8];

__device__ __forceinline__ void mma_bf16(float c[4],
        unsigned a0, unsigned a1, unsigned a2, unsigned a3,
        unsigned b0, unsigned b1) {
    asm volatile("mma.sync.aligned.m16n8k16.row.col.f32.bf16.bf16.f32 "
                 "{%0,%1,%2,%3},{%4,%5,%6,%7},{%8,%9},{%0,%1,%2,%3};"
                 : "+f"(c[0]), "+f"(c[1]), "+f"(c[2]), "+f"(c[3])
                 : "r"(a0), "r"(a1), "r"(a2), "r"(a3), "r"(b0), "r"(b1));
}
__device__ __forceinline__ void ldsm4(unsigned &r0, unsigned &r1, unsigned &r2, unsigned &r3,
                                      const void* p) {
    unsigned a = (unsigned)__cvta_generic_to_shared(p);
    asm volatile("ldmatrix.sync.aligned.m8n8.x4.shared.b16 {%0,%1,%2,%3}, [%4];"
                 : "=r"(r0), "=r"(r1), "=r"(r2), "=r"(r3) : "r"(a));
}
__device__ __forceinline__ void ldsm2(unsigned &r0, unsigned &r1, const void* p) {
    unsigned a = (unsigned)__cvta_generic_to_shared(p);
    asm volatile("ldmatrix.sync.aligned.m8n8.x2.shared.b16 {%0,%1}, [%2];"
                 : "=r"(r0), "=r"(r1) : "r"(a));
}
__device__ __forceinline__ void cpa16(void* dst, const void* src, bool p) {
    unsigned d = (unsigned)__cvta_generic_to_shared(dst);
    int sz = p ? 16 : 0;
    asm volatile("cp.async.ca.shared.global [%0], [%1], 16, %2;"
                 :: "r"(d), "l"(src), "r"(sz) : "memory");
}
__device__ __forceinline__ unsigned bf2pack(float lo, float hi) {
    unsigned r;
    asm("cvt.rn.bf16x2.f32 %0, %1, %2;" : "=r"(r) : "f"(hi), "f"(lo));
    return r;
}
__device__ __forceinline__ unsigned long long bfup(unsigned w) {
    unsigned long long p;
    unsigned lo = w << 16, hi = w & 0xffff0000u;
    asm("mov.b64 %0, {%1, %2};" : "=l"(p) : "r"(lo), "r"(hi));
    return p;
}
__device__ __forceinline__ unsigned long long addx2(unsigned long long a, unsigned long long b) {
    unsigned long long r;
    asm("add.rn.f32x2 %0, %1, %2;" : "=l"(r) : "l"(a), "l"(b));
    return r;
}
__device__ __forceinline__ void unpx2(float &lo, float &hi, unsigned long long p) {
    asm("mov.b64 {%0, %1}, %2;" : "=f"(lo), "=f"(hi) : "l"(p));
}

// ---------------- K1: block-range front (x pack | deg+slot+mask | w pack) ----
#define FB_X 1024
#define FB_E 768
#define FB_W 256
#define PREP_W1 (256 * HH)
#define PREP_W2 (96 * HH)
__global__ void k_front(const int* __restrict__ row,
                        const unsigned int* __restrict__ mw,
                        const float* __restrict__ x,
                        const float* __restrict__ w1n, const float* __restrict__ w1s,
                        const float* __restrict__ w2n, const float* __restrict__ w2s) {
    int b = blockIdx.x, t = threadIdx.x;
    if (b < FB_X) {
        int stride = FB_X * 256;
        const float4* xs = reinterpret_cast<const float4*>(x);
        for (int i = b * 256 + t; i < NN * DIN / 4; i += stride) {
            float4 v = xs[i];
            uint2 r;
            r.x = bf2pack(v.x, v.y);
            r.y = bf2pack(v.z, v.w);
            reinterpret_cast<uint2*>(g_xh)[i] = r;
        }
    } else if (b < FB_X + FB_E) {
        int i0 = (b - FB_X) * 256 + t, stride = FB_E * 256;
        for (int i = i0; i < EE; i += stride)
            g_slot[i] = atomicAdd(&g_meta[row[i]], 1);
        for (int i = i0; i < NN / 4; i += stride)
            if (mw[i] > 1u) g_meta[NN] = 1;
    } else {
        int i0 = (b - FB_X - FB_E) * 256 + t, stride = FB_W * 256;
        for (int i = i0; i < PREP_W1 + PREP_W2; i += stride) {
            if (i < PREP_W1) {
                int n = i >> 8, k = i & 255;
                float v = (k < DIN) ? w1n[k * HH + n] : w1s[(k - DIN) * HH + n];
                g_w1t[i] = __float2bfloat16(v);
            } else {
                int j = i - PREP_W1;
                int n = j >> 8, k = j & 255;
                float v = 0.f;
                if (n < CP) { if (n < CC) v = w2n[k * CC + n]; }
                else        { int n2 = n - CP; if (n2 < CC) v = w2s[k * CC + n2]; }
                g_w2t[j] = __float2bfloat16(v);
            }
        }
    }
}

// ---------------- K2: block scan + last-block finalize -----------------------
__global__ void k_scan() {
    __shared__ int sh[256];
    __shared__ int islast;
    int i = blockIdx.x * 256 + threadIdx.x;
    int v = (i < NN) ? g_meta[i] : 0;
    sh[threadIdx.x] = v;
    __syncthreads();
    for (int o = 1; o < 256; o <<= 1) {
        int t = (threadIdx.x >= o) ? sh[threadIdx.x - o] : 0;
        __syncthreads();
        sh[threadIdx.x] += t;
        __syncthreads();
    }
    int incl = sh[threadIdx.x];
    if (i < NN) g_rp[i] = incl - v;
    if (threadIdx.x == 255) g_bsum[blockIdx.x] = incl;

    __threadfence();
    if (threadIdx.x == 0) {
        int old = atomicAdd(&g_meta[NN + 1], 1);
        islast = (old == gridDim.x - 1);
    }
    __syncthreads();
    if (islast) {
        int b = threadIdx.x;
        int bv = (b < NB) ? g_bsum[b] : 0;
        sh[b] = bv;
        __syncthreads();
        for (int o = 1; o < 256; o <<= 1) {
            int t = (b >= o) ? sh[b - o] : 0;
            __syncthreads();
            sh[b] += t;
            __syncthreads();
        }
        if (b < NB) g_bsum[b] = sh[b] - bv;
    }
}

// ---------------- K3: fill adjacency (atomic-free) ---------------------------
__global__ void k_fill(const int* __restrict__ row, const int* __restrict__ col) {
    int e = blockIdx.x * blockDim.x + threadIdx.x;
    if (e >= EE) return;
    int r = row[e];
    g_adj[g_rp[r] + g_bsum[r >> 8] + g_slot[e]] = col[e];
}

// ---------------- K4: agg1 (R9 form: warp/node, 2 edges/iter, f32x2) ---------
__global__ void k_agg1() {
    int w = (blockIdx.x * blockDim.x + threadIdx.x) >> 5;
    int lane = threadIdx.x & 31;
    if (w >= NN) return;
    int d = g_meta[w];
    int start = g_rp[w] + g_bsum[w >> 8];
    int e = lane >> 4, c = lane & 15;
    unsigned long long acc0 = 0, acc1 = 0, acc2 = 0, acc3 = 0;
    for (int j = 0; j < d; j += 2) {
        int jj = j + e;
        if (jj < d) {
            int s = g_adj[start + jj];
            uint4 v = reinterpret_cast<const uint4*>(g_xh + (size_t)s * DIN)[c];
            acc0 = addx2(acc0, bfup(v.x));
            acc1 = addx2(acc1, bfup(v.y));
            acc2 = addx2(acc2, bfup(v.z));
            acc3 = addx2(acc3, bfup(v.w));
        }
    }
    acc0 = addx2(acc0, __shfl_xor_sync(0xffffffffu, acc0, 16));
    acc1 = addx2(acc1, __shfl_xor_sync(0xffffffffu, acc1, 16));
    acc2 = addx2(acc2, __shfl_xor_sync(0xffffffffu, acc2, 16));
    acc3 = addx2(acc3, __shfl_xor_sync(0xffffffffu, acc3, 16));
    if (e == 0) {
        float inv = d > 0 ? 1.0f / (float)d : 0.f;
        float lo, hi;
        uint4 r;
        unpx2(lo, hi, acc0); r.x = bf2pack(lo * inv, hi * inv);
        unpx2(lo, hi, acc1); r.y = bf2pack(lo * inv, hi * inv);
        unpx2(lo, hi, acc2); r.z = bf2pack(lo * inv, hi * inv);
        unpx2(lo, hi, acc3); r.w = bf2pack(lo * inv, hi * inv);
        reinterpret_cast<uint4*>(g_aggb + (size_t)w * DIN)[c] = r;
    }
}

// ---------------- GEMM1 (bf16 mma, 3-stage): h1 = relu([aggb|xh]@w1t^T + b) --
#define G1_SMEM (3*128*72*2 + 3*128*72*2 + 128*4)
__global__ __launch_bounds__(256) void k_gemm1(
        const float* __restrict__ b1n, const float* __restrict__ b1s) {
    extern __shared__ __nv_bfloat16 sm[];
    __nv_bfloat16* As = sm;
    __nv_bfloat16* Bs = sm + 3 * 128 * 72;
    float* sbias = reinterpret_cast<float*>(Bs + 3 * 128 * 72);

    int tid  = threadIdx.x;
    int row0 = blockIdx.y * 128;
    int col0 = blockIdx.x * 128;
    if (tid < 128) sbias[tid] = b1n[col0 + tid] + b1s[col0 + tid];

    int lane = tid & 31, wid = tid >> 5;
    int m_w = (wid & 1) * 64;
    int n_w = (wid >> 1) * 32;

#define AS1(s,m,k) (As + ((s)*128 + (m))*72 + (k))
#define BS1(s,n,k) (Bs + ((s)*128 + (n))*72 + (k))

    auto load_tiles = [&](int s, int kt) {
        #pragma unroll
        for (int i = 0; i < 4; ++i) {
            int idx = tid + i * 256;
            int r = idx >> 3, c = (idx & 7) * 8;
            int gm = row0 + r;
            bool p = gm < NN;
            int gmc = p ? gm : 0;
            const __nv_bfloat16* src = (kt < 2)
                ? g_aggb + (size_t)gmc * DIN + kt * 64 + c
                : g_xh   + (size_t)gmc * DIN + (kt - 2) * 64 + c;
            cpa16(AS1(s, r, c), src, p);
        }
        #pragma unroll
        for (int i = 0; i < 4; ++i) {
            int idx = tid + i * 256;
            int r = idx >> 3, c = (idx & 7) * 8;
            cpa16(BS1(s, r, c), g_w1t + (size_t)(col0 + r) * 256 + kt * 64 + c, true);
        }
    };

    float acc[4][4][4] = {};
    load_tiles(0, 0);
    asm volatile("cp.async.commit_group;" ::: "memory");
    load_tiles(1, 1);
    asm volatile("cp.async.commit_group;" ::: "memory");

    for (int kt = 0; kt < 4; ++kt) {
        if (kt + 2 < 4) load_tiles((kt + 2) % 3, kt + 2);
        asm volatile("cp.async.commit_group;" ::: "memory");
        asm volatile("cp.async.wait_group 2;" ::: "memory");
        __syncthreads();
        int buf = kt % 3;
        #pragma unroll
        for (int ks = 0; ks < 4; ++ks) {
            int kk = ks * 16;
            unsigned af[4][4];
            #pragma unroll
            for (int mt = 0; mt < 4; ++mt) {
                int m = m_w + mt * 16 + (lane & 15);
                int c = kk + (lane >> 4) * 8;
                ldsm4(af[mt][0], af[mt][1], af[mt][2], af[mt][3], AS1(buf, m, c));
            }
            unsigned bf[4][2];
            #pragma unroll
            for (int nt = 0; nt < 4; ++nt) {
                int n = n_w + nt * 8 + (lane & 7);
                int c = kk + ((lane >> 3) & 1) * 8;
                ldsm2(bf[nt][0], bf[nt][1], BS1(buf, n, c));
            }
            #pragma unroll
            for (int mt = 0; mt < 4; ++mt)
                #pragma unroll
                for (int nt = 0; nt < 4; ++nt)
                    mma_bf16(acc[mt][nt], af[mt][0], af[mt][1], af[mt][2], af[mt][3],
                             bf[nt][0], bf[nt][1]);
        }
        __syncthreads();
    }

    int g = lane >> 2, tg = lane & 3;
    #pragma unroll
    for (int mt = 0; mt < 4; ++mt) {
        int mb = row0 + m_w + mt * 16 + g;
        #pragma unroll
        for (int nt = 0; nt < 4; ++nt) {
            int nl = n_w + nt * 8 + 2 * tg;
            int gn = col0 + nl;
            float b0 = sbias[nl], b1 = sbias[nl + 1];
            if (mb < NN) {
                unsigned r = bf2pack(fmaxf(acc[mt][nt][0] + b0, 0.f),
                                     fmaxf(acc[mt][nt][1] + b1, 0.f));
                *reinterpret_cast<unsigned*>(g_h1b + (size_t)mb * HH + gn) = r;
            }
            if (mb + 8 < NN) {
                unsigned r = bf2pack(fmaxf(acc[mt][nt][2] + b0, 0.f),
                                     fmaxf(acc[mt][nt][3] + b1, 0.f));
                *reinterpret_cast<unsigned*>(g_h1b + (size_t)(mb + 8) * HH + gn) = r;
            }
        }
    }
}

// ---------------- GEMM2 (bf16 mma): [z|s] = h1b @ w2t^T ----------------------
#define G2_SMEM (2*128*72*2 + 2*96*72*2)
__global__ __launch_bounds__(256) void k_gemm2() {
    extern __shared__ __nv_bfloat16 sm[];
    __nv_bfloat16* As = sm;
    __nv_bfloat16* Bs = sm + 2 * 128 * 72;

    int tid  = threadIdx.x;
    int row0 = blockIdx.y * 128;
    int lane = tid & 31, wid = tid >> 5;
    int m_w = (wid & 3) * 32;
    int n_w = (wid >> 2) * 48;

#define AS2(s,m,k) (As + ((s)*128 + (m))*72 + (k))
#define BS2(s,n,k) (Bs + ((s)*96 + (n))*72 + (k))

    auto load_tiles = [&](int s, int kt) {
        #pragma unroll
        for (int i = 0; i < 4; ++i) {
            int idx = tid + i * 256;
            int r = idx >> 3, c = (idx & 7) * 8;
            int gm = row0 + r;
            bool p = gm < NN;
            int gmc = p ? gm : 0;
            cpa16(AS2(s, r, c), g_h1b + (size_t)gmc * HH + kt * 64 + c, p);
        }
        #pragma unroll
        for (int i = 0; i < 3; ++i) {
            int idx = tid + i * 256;
            int r = idx >> 3, c = (idx & 7) * 8;
            cpa16(BS2(s, r, c), g_w2t + (size_t)r * 256 + kt * 64 + c, true);
        }
    };

    float acc[2][6][4] = {};
    load_tiles(0, 0);
    asm volatile("cp.async.commit_group;" ::: "memory");

    for (int kt = 0; kt < 4; ++kt) {
        if (kt + 1 < 4) {
            load_tiles((kt + 1) & 1, kt + 1);
            asm volatile("cp.async.commit_group;" ::: "memory");
            asm volatile("cp.async.wait_group 1;" ::: "memory");
        } else {
            asm volatile("cp.async.wait_group 0;" ::: "memory");
        }
        __syncthreads();
        int buf = kt & 1;
        #pragma unroll
        for (int ks = 0; ks < 4; ++ks) {
            int kk = ks * 16;
            unsigned af[2][4];
            #pragma unroll
            for (int mt = 0; mt < 2; ++mt) {
                int m = m_w + mt * 16 + (lane & 15);
                int c = kk + (lane >> 4) * 8;
                ldsm4(af[mt][0], af[mt][1], af[mt][2], af[mt][3], AS2(buf, m, c));
            }
            unsigned bf[6][2];
            #pragma unroll
            for (int nt = 0; nt < 6; ++nt) {
                int n = n_w + nt * 8 + (lane & 7);
                int c = kk + ((lane >> 3) & 1) * 8;
                ldsm2(bf[nt][0], bf[nt][1], BS2(buf, n, c));
            }
            #pragma unroll
            for (int mt = 0; mt < 2; ++mt)
                #pragma unroll
                for (int nt = 0; nt < 6; ++nt)
                    mma_bf16(acc[mt][nt], af[mt][0], af[mt][1], af[mt][2], af[mt][3],
                             bf[nt][0], bf[nt][1]);
        }
        __syncthreads();
    }

    int g = lane >> 2, tg = lane & 3;
    #pragma unroll
    for (int mt = 0; mt < 2; ++mt) {
        int mb = row0 + m_w + mt * 16 + g;
        #pragma unroll
        for (int nt = 0; nt < 6; ++nt) {
            int n = n_w + nt * 8 + 2 * tg;
            if (n < CP) {
                if (mb < NN)
                    *reinterpret_cast<unsigned*>(g_zb + (size_t)mb * CPZ + n) =
                        bf2pack(acc[mt][nt][0], acc[mt][nt][1]);
                if (mb + 8 < NN)
                    *reinterpret_cast<unsigned*>(g_zb + (size_t)(mb + 8) * CPZ + n) =
                        bf2pack(acc[mt][nt][2], acc[mt][nt][3]);
            } else {
                int n2 = n - CP;
                if (mb < NN)
                    *reinterpret_cast<float2*>(g_s + (size_t)mb * CP + n2) =
                        make_float2(acc[mt][nt][0], acc[mt][nt][1]);
                if (mb + 8 < NN)
                    *reinterpret_cast<float2*>(g_s + (size_t)(mb + 8) * CP + n2) =
                        make_float2(acc[mt][nt][2], acc[mt][nt][3]);
            }
        }
    }
}

// ---------------- fused agg2 + loss + finalize (R9 form) ---------------------
__global__ void k_loss(const int* __restrict__ y,
                       const void* __restrict__ maskp,
                       const float* __restrict__ b2n,
                       const float* __restrict__ b2s,
                       float* __restrict__ out) {
    __shared__ float sz[8][64];
    __shared__ int islast;
    int w = (blockIdx.x * blockDim.x + threadIdx.x) >> 5;
    int lane = threadIdx.x & 31;
    int wl = (threadIdx.x >> 5) & 7;

    if (w < NN) {
        int d = g_meta[w];
        int start = g_rp[w] + g_bsum[w >> 8];
        int e = lane >> 3, c = lane & 7;
        unsigned long long acc0 = 0, acc1 = 0, acc2 = 0, acc3 = 0;
        for (int j = 0; j < d; j += 4) {
            int jj = j + e;
            if (jj < d) {
                int s = g_adj[start + jj];
                uint4 v = reinterpret_cast<const uint4*>(g_zb + (size_t)s * CPZ)[c];
                acc0 = addx2(acc0, bfup(v.x));
                acc1 = addx2(acc1, bfup(v.y));
                acc2 = addx2(acc2, bfup(v.z));
                acc3 = addx2(acc3, bfup(v.w));
            }
        }
        acc0 = addx2(acc0, __shfl_xor_sync(0xffffffffu, acc0, 8));
        acc1 = addx2(acc1, __shfl_xor_sync(0xffffffffu, acc1, 8));
        acc2 = addx2(acc2, __shfl_xor_sync(0xffffffffu, acc2, 8));
        acc3 = addx2(acc3, __shfl_xor_sync(0xffffffffu, acc3, 8));
        acc0 = addx2(acc0, __shfl_xor_sync(0xffffffffu, acc0, 16));
        acc1 = addx2(acc1, __shfl_xor_sync(0xffffffffu, acc1, 16));
        acc2 = addx2(acc2, __shfl_xor_sync(0xffffffffu, acc2, 16));
        acc3 = addx2(acc3, __shfl_xor_sync(0xffffffffu, acc3, 16));
        if (e == 0) {
            float inv = d > 0 ? 1.0f / (float)d : 0.f;
            float lo, hi;
            unpx2(lo, hi, acc0); sz[wl][c * 8 + 0] = lo * inv; sz[wl][c * 8 + 1] = hi * inv;
            unpx2(lo, hi, acc1); sz[wl][c * 8 + 2] = lo * inv; sz[wl][c * 8 + 3] = hi * inv;
            unpx2(lo, hi, acc2); sz[wl][c * 8 + 4] = lo * inv; sz[wl][c * 8 + 5] = hi * inv;
            unpx2(lo, hi, acc3); sz[wl][c * 8 + 6] = lo * inv; sz[wl][c * 8 + 7] = hi * inv;
        }
        __syncwarp();

        const float* ss = g_s + (size_t)w * CP;
        int j2 = lane + 32;
        float l1 = sz[wl][lane] + ss[lane] + b2n[lane] + b2s[lane];
        float l2 = -1e30f;
        if (j2 < CC) l2 = sz[wl][j2] + ss[j2] + b2n[j2] + b2s[j2];

        float m = fmaxf(l1, l2);
        #pragma unroll
        for (int o = 16; o; o >>= 1) m = fmaxf(m, __shfl_xor_sync(0xffffffffu, m, o));
        float se = expf(l1 - m) + ((j2 < CC) ? expf(l2 - m) : 0.f);
        #pragma unroll
        for (int o = 16; o; o >>= 1) se += __shfl_xor_sync(0xffffffffu, se, o);

        if (lane == 0) {
            bool bytemode = (g_meta[NN] != 0);
            bool tm = bytemode ? (((const unsigned char*)maskp)[w] != 0)
                               : (((const int*)maskp)[w] != 0);
            if (tm) {
                int yy = y[w];
                float ly = sz[wl][yy] + ss[yy] + b2n[yy] + b2s[yy];
                float nll = m + logf(se) - ly;
                atomicAdd(reinterpret_cast<float*>(&g_meta[NN + 2]), nll);
                atomicAdd(reinterpret_cast<float*>(&g_meta[NN + 3]), 1.0f);
            }
        }
    }

    __threadfence();
    __syncthreads();
    if (threadIdx.x == 0) {
        int old = atomicAdd(&g_meta[NN + 4], 1);
        islast = (old == gridDim.x - 1);
    }
    __syncthreads();
    if (islast && threadIdx.x == 0) {
        float a = __int_as_float(g_meta[NN + 2]);
        float c = __int_as_float(g_meta[NN + 3]);
        out[0] = a / fmaxf(c, 1.0f);
    }
}

// ---------------- host launcher ----------------------------------------------
extern "C" void kernel_launch(void* const* d_in, const int* in_sizes, int n_in,
                              void* d_out, int out_size) {
    const float* x    = (const float*)d_in[0];
    const int*   row  = (const int*)d_in[1];
    const int*   col  = (const int*)d_in[2];
    const int*   y    = (const int*)d_in[3];
    const void*  mask = d_in[4];
    const float* w1n = (const float*)d_in[5];
    const float* b1n = (const float*)d_in[6];
    const float* w1s = (const float*)d_in[7];
    const float* b1s = (const float*)d_in[8];
    const float* w2n = (const float*)d_in[9];
    const float* b2n = (const float*)d_in[10];
    const float* w2s = (const float*)d_in[11];
    const float* b2s = (const float*)d_in[12];
    float* out = (float*)d_out;

    static int cfg = 0;
    if (!cfg) {
        cudaFuncSetAttribute(k_gemm1, cudaFuncAttributeMaxDynamicSharedMemorySize, G1_SMEM);
        cudaFuncSetAttribute(k_gemm2, cudaFuncAttributeMaxDynamicSharedMemorySize, G2_SMEM);
        cfg = 1;
    }

    void* p_meta;
    cudaGetSymbolAddress(&p_meta, g_meta);
    cudaMemsetAsync(p_meta, 0, (NN + 8) * sizeof(int));

    k_front<<<FB_X + FB_E + FB_W, 256>>>(row, (const unsigned int*)mask, x,
                                         w1n, w1s, w2n, w2s);
    k_scan<<<NB, 256>>>();
    k_fill<<<(EE + 255) / 256, 256>>>(row, col);
    k_agg1<<<(NN * 32 + 511) / 512, 512>>>();
    {
        dim3 grid(HH / 128, (NN + 127) / 128);
        k_gemm1<<<grid, 256, G1_SMEM>>>(b1n, b1s);
    }
    {
        dim3 grid(1, (NN + 127) / 128);
        k_gemm2<<<grid, 256, G2_SMEM>>>();
    }
    k_loss<<<(NN * 32 + 255) / 256, 256>>>(y, mask, b2n, b2s, out);
}

// round 14
// speedup vs baseline: 1.0603x; 1.0169x over previous
#include <cuda_runtime.h>
#include <cuda_bf16.h>
#include <math.h>

#define NN   50000
#define EE   800000
#define DIN  128
#define HH   256
#define CC   47
#define CP   48
#define CPZ  64    // padded bf16 z row (128 B)
#define NB   ((NN + 255) / 256)   // 196 scan blocks

// ---------------- scratch (device globals) -----------------------------------
__device__ __nv_bfloat16 g_xh  [(size_t)NN * DIN];
__device__ __nv_bfloat16 g_aggb[(size_t)NN * DIN];
__device__ __nv_bfloat16 g_h1b [(size_t)NN * HH];
__device__ __nv_bfloat16 g_w1t [256 * HH];           // [n=256][k=256]
__device__ __nv_bfloat16 g_w2t [96 * HH];            // [n=96][k=256]
__device__ __nv_bfloat16 g_zb  [(size_t)NN * CPZ];   // cols 48-63 stay 0
__device__ float g_s   [(size_t)NN * CP];
__device__ int   g_rp  [NN];
__device__ int   g_bsum[256];
__device__ int   g_adj [EE];
__device__ int   g_slot[EE];                         // per-edge slot within its node
// g_meta: [0,NN)=deg, [NN+0]=bytemask, [NN+1]=scan done,
//         [NN+2..3]=loss acc (f32 bits), [NN+4]=loss blocksDone
__device__ int   g_meta[NN + 8];

__device__ __forceinline__ void mma_bf16(float c[4],
        unsigned a0, unsigned a1, unsigned a2, unsigned a3,
        unsigned b0, unsigned b1) {
    asm volatile("mma.sync.aligned.m16n8k16.row.col.f32.bf16.bf16.f32 "
                 "{%0,%1,%2,%3},{%4,%5,%6,%7},{%8,%9},{%0,%1,%2,%3};"
                 : "+f"(c[0]), "+f"(c[1]), "+f"(c[2]), "+f"(c[3])
                 : "r"(a0), "r"(a1), "r"(a2), "r"(a3), "r"(b0), "r"(b1));
}
__device__ __forceinline__ void ldsm4(unsigned &r0, unsigned &r1, unsigned &r2, unsigned &r3,
                                      const void* p) {
    unsigned a = (unsigned)__cvta_generic_to_shared(p);
    asm volatile("ldmatrix.sync.aligned.m8n8.x4.shared.b16 {%0,%1,%2,%3}, [%4];"
                 : "=r"(r0), "=r"(r1), "=r"(r2), "=r"(r3) : "r"(a));
}
__device__ __forceinline__ void ldsm2(unsigned &r0, unsigned &r1, const void* p) {
    unsigned a = (unsigned)__cvta_generic_to_shared(p);
    asm volatile("ldmatrix.sync.aligned.m8n8.x2.shared.b16 {%0,%1}, [%2];"
                 : "=r"(r0), "=r"(r1) : "r"(a));
}
__device__ __forceinline__ void cpa16(void* dst, const void* src, bool p) {
    unsigned d = (unsigned)__cvta_generic_to_shared(dst);
    int sz = p ? 16 : 0;
    asm volatile("cp.async.ca.shared.global [%0], [%1], 16, %2;"
                 :: "r"(d), "l"(src), "r"(sz) : "memory");
}
__device__ __forceinline__ unsigned bf2pack(float lo, float hi) {
    unsigned r;
    asm("cvt.rn.bf16x2.f32 %0, %1, %2;" : "=r"(r) : "f"(hi), "f"(lo));
    return r;
}
// bf16x2 packed add (both halves at once, no unpack)
__device__ __forceinline__ unsigned hadd2(unsigned a, unsigned b) {
    unsigned r;
    asm("add.rn.bf16x2 %0, %1, %2;" : "=r"(r) : "r"(a), "r"(b));
    return r;
}
__device__ __forceinline__ unsigned long long bfup(unsigned w) {
    unsigned long long p;
    unsigned lo = w << 16, hi = w & 0xffff0000u;
    asm("mov.b64 %0, {%1, %2};" : "=l"(p) : "r"(lo), "r"(hi));
    return p;
}
__device__ __forceinline__ unsigned long long addx2(unsigned long long a, unsigned long long b) {
    unsigned long long r;
    asm("add.rn.f32x2 %0, %1, %2;" : "=l"(r) : "l"(a), "l"(b));
    return r;
}
__device__ __forceinline__ void unpx2(float &lo, float &hi, unsigned long long p) {
    asm("mov.b64 {%0, %1}, %2;" : "=f"(lo), "=f"(hi) : "l"(p));
}

// ---------------- K1: block-range front (x pack | deg+slot+mask | w pack) ----
#define FB_X 1024
#define FB_E 768
#define FB_W 256
#define PREP_W1 (256 * HH)
#define PREP_W2 (96 * HH)
__global__ void k_front(const int* __restrict__ row,
                        const unsigned int* __restrict__ mw,
                        const float* __restrict__ x,
                        const float* __restrict__ w1n, const float* __restrict__ w1s,
                        const float* __restrict__ w2n, const float* __restrict__ w2s) {
    int b = blockIdx.x, t = threadIdx.x;
    if (b < FB_X) {
        int stride = FB_X * 256;
        const float4* xs = reinterpret_cast<const float4*>(x);
        for (int i = b * 256 + t; i < NN * DIN / 4; i += stride) {
            float4 v = xs[i];
            uint2 r;
            r.x = bf2pack(v.x, v.y);
            r.y = bf2pack(v.z, v.w);
            reinterpret_cast<uint2*>(g_xh)[i] = r;
        }
    } else if (b < FB_X + FB_E) {
        int i0 = (b - FB_X) * 256 + t, stride = FB_E * 256;
        for (int i = i0; i < EE; i += stride)
            g_slot[i] = atomicAdd(&g_meta[row[i]], 1);
        for (int i = i0; i < NN / 4; i += stride)
            if (mw[i] > 1u) g_meta[NN] = 1;
    } else {
        int i0 = (b - FB_X - FB_E) * 256 + t, stride = FB_W * 256;
        for (int i = i0; i < PREP_W1 + PREP_W2; i += stride) {
            if (i < PREP_W1) {
                int n = i >> 8, k = i & 255;
                float v = (k < DIN) ? w1n[k * HH + n] : w1s[(k - DIN) * HH + n];
                g_w1t[i] = __float2bfloat16(v);
            } else {
                int j = i - PREP_W1;
                int n = j >> 8, k = j & 255;
                float v = 0.f;
                if (n < CP) { if (n < CC) v = w2n[k * CC + n]; }
                else        { int n2 = n - CP; if (n2 < CC) v = w2s[k * CC + n2]; }
                g_w2t[j] = __float2bfloat16(v);
            }
        }
    }
}

// ---------------- K2: block scan + last-block finalize -----------------------
__global__ void k_scan() {
    __shared__ int sh[256];
    __shared__ int islast;
    int i = blockIdx.x * 256 + threadIdx.x;
    int v = (i < NN) ? g_meta[i] : 0;
    sh[threadIdx.x] = v;
    __syncthreads();
    for (int o = 1; o < 256; o <<= 1) {
        int t = (threadIdx.x >= o) ? sh[threadIdx.x - o] : 0;
        __syncthreads();
        sh[threadIdx.x] += t;
        __syncthreads();
    }
    int incl = sh[threadIdx.x];
    if (i < NN) g_rp[i] = incl - v;
    if (threadIdx.x == 255) g_bsum[blockIdx.x] = incl;

    __threadfence();
    if (threadIdx.x == 0) {
        int old = atomicAdd(&g_meta[NN + 1], 1);
        islast = (old == gridDim.x - 1);
    }
    __syncthreads();
    if (islast) {
        int b = threadIdx.x;
        int bv = (b < NB) ? g_bsum[b] : 0;
        sh[b] = bv;
        __syncthreads();
        for (int o = 1; o < 256; o <<= 1) {
            int t = (b >= o) ? sh[b - o] : 0;
            __syncthreads();
            sh[b] += t;
            __syncthreads();
        }
        if (b < NB) g_bsum[b] = sh[b] - bv;
    }
}

// ---------------- K3: fill adjacency (atomic-free) ---------------------------
__global__ void k_fill(const int* __restrict__ row, const int* __restrict__ col) {
    int e = blockIdx.x * blockDim.x + threadIdx.x;
    if (e >= EE) return;
    int r = row[e];
    g_adj[g_rp[r] + g_bsum[r >> 8] + g_slot[e]] = col[e];
}

// ---------------- K4: agg1 (warp/node, 2 edges/iter, bf16x2 accumulation) ----
__global__ void k_agg1() {
    int w = (blockIdx.x * blockDim.x + threadIdx.x) >> 5;
    int lane = threadIdx.x & 31;
    if (w >= NN) return;
    int d = g_meta[w];
    int start = g_rp[w] + g_bsum[w >> 8];
    int e = lane >> 4, c = lane & 15;
    unsigned a0 = 0, a1 = 0, a2 = 0, a3 = 0;   // bf16x2 accumulators
    for (int j = 0; j < d; j += 2) {
        int jj = j + e;
        if (jj < d) {
            int s = g_adj[start + jj];
            uint4 v = __ldg(reinterpret_cast<const uint4*>(g_xh + (size_t)s * DIN) + c);
            a0 = hadd2(a0, v.x);
            a1 = hadd2(a1, v.y);
            a2 = hadd2(a2, v.z);
            a3 = hadd2(a3, v.w);
        }
    }
    a0 = hadd2(a0, __shfl_xor_sync(0xffffffffu, a0, 16));
    a1 = hadd2(a1, __shfl_xor_sync(0xffffffffu, a1, 16));
    a2 = hadd2(a2, __shfl_xor_sync(0xffffffffu, a2, 16));
    a3 = hadd2(a3, __shfl_xor_sync(0xffffffffu, a3, 16));
    if (e == 0) {
        float inv = d > 0 ? 1.0f / (float)d : 0.f;
        uint4 r;
        float2 f;
        f = __bfloat1622float2(*reinterpret_cast<__nv_bfloat162*>(&a0));
        r.x = bf2pack(f.x * inv, f.y * inv);
        f = __bfloat1622float2(*reinterpret_cast<__nv_bfloat162*>(&a1));
        r.y = bf2pack(f.x * inv, f.y * inv);
        f = __bfloat1622float2(*reinterpret_cast<__nv_bfloat162*>(&a2));
        r.z = bf2pack(f.x * inv, f.y * inv);
        f = __bfloat1622float2(*reinterpret_cast<__nv_bfloat162*>(&a3));
        r.w = bf2pack(f.x * inv, f.y * inv);
        reinterpret_cast<uint4*>(g_aggb + (size_t)w * DIN)[c] = r;
    }
}

// ---------------- GEMM1 (bf16 mma, 3-stage): h1 = relu([aggb|xh]@w1t^T + b) --
#define G1_SMEM (3*128*72*2 + 3*128*72*2 + 128*4)
__global__ __launch_bounds__(256) void k_gemm1(
        const float* __restrict__ b1n, const float* __restrict__ b1s) {
    extern __shared__ __nv_bfloat16 sm[];
    __nv_bfloat16* As = sm;
    __nv_bfloat16* Bs = sm + 3 * 128 * 72;
    float* sbias = reinterpret_cast<float*>(Bs + 3 * 128 * 72);

    int tid  = threadIdx.x;
    int row0 = blockIdx.y * 128;
    int col0 = blockIdx.x * 128;
    if (tid < 128) sbias[tid] = b1n[col0 + tid] + b1s[col0 + tid];

    int lane = tid & 31, wid = tid >> 5;
    int m_w = (wid & 1) * 64;
    int n_w = (wid >> 1) * 32;

#define AS1(s,m,k) (As + ((s)*128 + (m))*72 + (k))
#define BS1(s,n,k) (Bs + ((s)*128 + (n))*72 + (k))

    auto load_tiles = [&](int s, int kt) {
        #pragma unroll
        for (int i = 0; i < 4; ++i) {
            int idx = tid + i * 256;
            int r = idx >> 3, c = (idx & 7) * 8;
            int gm = row0 + r;
            bool p = gm < NN;
            int gmc = p ? gm : 0;
            const __nv_bfloat16* src = (kt < 2)
                ? g_aggb + (size_t)gmc * DIN + kt * 64 + c
                : g_xh   + (size_t)gmc * DIN + (kt - 2) * 64 + c;
            cpa16(AS1(s, r, c), src, p);
        }
        #pragma unroll
        for (int i = 0; i < 4; ++i) {
            int idx = tid + i * 256;
            int r = idx >> 3, c = (idx & 7) * 8;
            cpa16(BS1(s, r, c), g_w1t + (size_t)(col0 + r) * 256 + kt * 64 + c, true);
        }
    };

    float acc[4][4][4] = {};
    load_tiles(0, 0);
    asm volatile("cp.async.commit_group;" ::: "memory");
    load_tiles(1, 1);
    asm volatile("cp.async.commit_group;" ::: "memory");

    for (int kt = 0; kt < 4; ++kt) {
        if (kt + 2 < 4) load_tiles((kt + 2) % 3, kt + 2);
        asm volatile("cp.async.commit_group;" ::: "memory");
        asm volatile("cp.async.wait_group 2;" ::: "memory");
        __syncthreads();
        int buf = kt % 3;
        #pragma unroll
        for (int ks = 0; ks < 4; ++ks) {
            int kk = ks * 16;
            unsigned af[4][4];
            #pragma unroll
            for (int mt = 0; mt < 4; ++mt) {
                int m = m_w + mt * 16 + (lane & 15);
                int c = kk + (lane >> 4) * 8;
                ldsm4(af[mt][0], af[mt][1], af[mt][2], af[mt][3], AS1(buf, m, c));
            }
            unsigned bf[4][2];
            #pragma unroll
            for (int nt = 0; nt < 4; ++nt) {
                int n = n_w + nt * 8 + (lane & 7);
                int c = kk + ((lane >> 3) & 1) * 8;
                ldsm2(bf[nt][0], bf[nt][1], BS1(buf, n, c));
            }
            #pragma unroll
            for (int mt = 0; mt < 4; ++mt)
                #pragma unroll
                for (int nt = 0; nt < 4; ++nt)
                    mma_bf16(acc[mt][nt], af[mt][0], af[mt][1], af[mt][2], af[mt][3],
                             bf[nt][0], bf[nt][1]);
        }
        __syncthreads();
    }

    int g = lane >> 2, tg = lane & 3;
    #pragma unroll
    for (int mt = 0; mt < 4; ++mt) {
        int mb = row0 + m_w + mt * 16 + g;
        #pragma unroll
        for (int nt = 0; nt < 4; ++nt) {
            int nl = n_w + nt * 8 + 2 * tg;
            int gn = col0 + nl;
            float b0 = sbias[nl], b1 = sbias[nl + 1];
            if (mb < NN) {
                unsigned r = bf2pack(fmaxf(acc[mt][nt][0] + b0, 0.f),
                                     fmaxf(acc[mt][nt][1] + b1, 0.f));
                *reinterpret_cast<unsigned*>(g_h1b + (size_t)mb * HH + gn) = r;
            }
            if (mb + 8 < NN) {
                unsigned r = bf2pack(fmaxf(acc[mt][nt][2] + b0, 0.f),
                                     fmaxf(acc[mt][nt][3] + b1, 0.f));
                *reinterpret_cast<unsigned*>(g_h1b + (size_t)(mb + 8) * HH + gn) = r;
            }
        }
    }
}

// ---------------- GEMM2 (bf16 mma): [z|s] = h1b @ w2t^T ----------------------
#define G2_SMEM (2*128*72*2 + 2*96*72*2)
__global__ __launch_bounds__(256) void k_gemm2() {
    extern __shared__ __nv_bfloat16 sm[];
    __nv_bfloat16* As = sm;
    __nv_bfloat16* Bs = sm + 2 * 128 * 72;

    int tid  = threadIdx.x;
    int row0 = blockIdx.y * 128;
    int lane = tid & 31, wid = tid >> 5;
    int m_w = (wid & 3) * 32;
    int n_w = (wid >> 2) * 48;

#define AS2(s,m,k) (As + ((s)*128 + (m))*72 + (k))
#define BS2(s,n,k) (Bs + ((s)*96 + (n))*72 + (k))

    auto load_tiles = [&](int s, int kt) {
        #pragma unroll
        for (int i = 0; i < 4; ++i) {
            int idx = tid + i * 256;
            int r = idx >> 3, c = (idx & 7) * 8;
            int gm = row0 + r;
            bool p = gm < NN;
            int gmc = p ? gm : 0;
            cpa16(AS2(s, r, c), g_h1b + (size_t)gmc * HH + kt * 64 + c, p);
        }
        #pragma unroll
        for (int i = 0; i < 3; ++i) {
            int idx = tid + i * 256;
            int r = idx >> 3, c = (idx & 7) * 8;
            cpa16(BS2(s, r, c), g_w2t + (size_t)r * 256 + kt * 64 + c, true);
        }
    };

    float acc[2][6][4] = {};
    load_tiles(0, 0);
    asm volatile("cp.async.commit_group;" ::: "memory");

    for (int kt = 0; kt < 4; ++kt) {
        if (kt + 1 < 4) {
            load_tiles((kt + 1) & 1, kt + 1);
            asm volatile("cp.async.commit_group;" ::: "memory");
            asm volatile("cp.async.wait_group 1;" ::: "memory");
        } else {
            asm volatile("cp.async.wait_group 0;" ::: "memory");
        }
        __syncthreads();
        int buf = kt & 1;
        #pragma unroll
        for (int ks = 0; ks < 4; ++ks) {
            int kk = ks * 16;
            unsigned af[2][4];
            #pragma unroll
            for (int mt = 0; mt < 2; ++mt) {
                int m = m_w + mt * 16 + (lane & 15);
                int c = kk + (lane >> 4) * 8;
                ldsm4(af[mt][0], af[mt][1], af[mt][2], af[mt][3], AS2(buf, m, c));
            }
            unsigned bf[6][2];
            #pragma unroll
            for (int nt = 0; nt < 6; ++nt) {
                int n = n_w + nt * 8 + (lane & 7);
                int c = kk + ((lane >> 3) & 1) * 8;
                ldsm2(bf[nt][0], bf[nt][1], BS2(buf, n, c));
            }
            #pragma unroll
            for (int mt = 0; mt < 2; ++mt)
                #pragma unroll
                for (int nt = 0; nt < 6; ++nt)
                    mma_bf16(acc[mt][nt], af[mt][0], af[mt][1], af[mt][2], af[mt][3],
                             bf[nt][0], bf[nt][1]);
        }
        __syncthreads();
    }

    int g = lane >> 2, tg = lane & 3;
    #pragma unroll
    for (int mt = 0; mt < 2; ++mt) {
        int mb = row0 + m_w + mt * 16 + g;
        #pragma unroll
        for (int nt = 0; nt < 6; ++nt) {
            int n = n_w + nt * 8 + 2 * tg;
            if (n < CP) {
                if (mb < NN)
                    *reinterpret_cast<unsigned*>(g_zb + (size_t)mb * CPZ + n) =
                        bf2pack(acc[mt][nt][0], acc[mt][nt][1]);
                if (mb + 8 < NN)
                    *reinterpret_cast<unsigned*>(g_zb + (size_t)(mb + 8) * CPZ + n) =
                        bf2pack(acc[mt][nt][2], acc[mt][nt][3]);
            } else {
                int n2 = n - CP;
                if (mb < NN)
                    *reinterpret_cast<float2*>(g_s + (size_t)mb * CP + n2) =
                        make_float2(acc[mt][nt][0], acc[mt][nt][1]);
                if (mb + 8 < NN)
                    *reinterpret_cast<float2*>(g_s + (size_t)(mb + 8) * CP + n2) =
                        make_float2(acc[mt][nt][2], acc[mt][nt][3]);
            }
        }
    }
}

// ---------------- fused agg2 + loss + finalize (R9 form, f32x2 accum) --------
__global__ void k_loss(const int* __restrict__ y,
                       const void* __restrict__ maskp,
                       const float* __restrict__ b2n,
                       const float* __restrict__ b2s,
                       float* __restrict__ out) {
    __shared__ float sz[8][64];
    __shared__ int islast;
    int w = (blockIdx.x * blockDim.x + threadIdx.x) >> 5;
    int lane = threadIdx.x & 31;
    int wl = (threadIdx.x >> 5) & 7;

    if (w < NN) {
        int d = g_meta[w];
        int start = g_rp[w] + g_bsum[w >> 8];
        int e = lane >> 3, c = lane & 7;
        unsigned long long acc0 = 0, acc1 = 0, acc2 = 0, acc3 = 0;
        for (int j = 0; j < d; j += 4) {
            int jj = j + e;
            if (jj < d) {
                int s = g_adj[start + jj];
                uint4 v = reinterpret_cast<const uint4*>(g_zb + (size_t)s * CPZ)[c];
                acc0 = addx2(acc0, bfup(v.x));
                acc1 = addx2(acc1, bfup(v.y));
                acc2 = addx2(acc2, bfup(v.z));
                acc3 = addx2(acc3, bfup(v.w));
            }
        }
        acc0 = addx2(acc0, __shfl_xor_sync(0xffffffffu, acc0, 8));
        acc1 = addx2(acc1, __shfl_xor_sync(0xffffffffu, acc1, 8));
        acc2 = addx2(acc2, __shfl_xor_sync(0xffffffffu, acc2, 8));
        acc3 = addx2(acc3, __shfl_xor_sync(0xffffffffu, acc3, 8));
        acc0 = addx2(acc0, __shfl_xor_sync(0xffffffffu, acc0, 16));
        acc1 = addx2(acc1, __shfl_xor_sync(0xffffffffu, acc1, 16));
        acc2 = addx2(acc2, __shfl_xor_sync(0xffffffffu, acc2, 16));
        acc3 = addx2(acc3, __shfl_xor_sync(0xffffffffu, acc3, 16));
        if (e == 0) {
            float inv = d > 0 ? 1.0f / (float)d : 0.f;
            float lo, hi;
            unpx2(lo, hi, acc0); sz[wl][c * 8 + 0] = lo * inv; sz[wl][c * 8 + 1] = hi * inv;
            unpx2(lo, hi, acc1); sz[wl][c * 8 + 2] = lo * inv; sz[wl][c * 8 + 3] = hi * inv;
            unpx2(lo, hi, acc2); sz[wl][c * 8 + 4] = lo * inv; sz[wl][c * 8 + 5] = hi * inv;
            unpx2(lo, hi, acc3); sz[wl][c * 8 + 6] = lo * inv; sz[wl][c * 8 + 7] = hi * inv;
        }
        __syncwarp();

        const float* ss = g_s + (size_t)w * CP;
        int j2 = lane + 32;
        float l1 = sz[wl][lane] + ss[lane] + b2n[lane] + b2s[lane];
        float l2 = -1e30f;
        if (j2 < CC) l2 = sz[wl][j2] + ss[j2] + b2n[j2] + b2s[j2];

        float m = fmaxf(l1, l2);
        #pragma unroll
        for (int o = 16; o; o >>= 1) m = fmaxf(m, __shfl_xor_sync(0xffffffffu, m, o));
        float se = expf(l1 - m) + ((j2 < CC) ? expf(l2 - m) : 0.f);
        #pragma unroll
        for (int o = 16; o; o >>= 1) se += __shfl_xor_sync(0xffffffffu, se, o);

        if (lane == 0) {
            bool bytemode = (g_meta[NN] != 0);
            bool tm = bytemode ? (((const unsigned char*)maskp)[w] != 0)
                               : (((const int*)maskp)[w] != 0);
            if (tm) {
                int yy = y[w];
                float ly = sz[wl][yy] + ss[yy] + b2n[yy] + b2s[yy];
                float nll = m + logf(se) - ly;
                atomicAdd(reinterpret_cast<float*>(&g_meta[NN + 2]), nll);
                atomicAdd(reinterpret_cast<float*>(&g_meta[NN + 3]), 1.0f);
            }
        }
    }

    __threadfence();
    __syncthreads();
    if (threadIdx.x == 0) {
        int old = atomicAdd(&g_meta[NN + 4], 1);
        islast = (old == gridDim.x - 1);
    }
    __syncthreads();
    if (islast && threadIdx.x == 0) {
        float a = __int_as_float(g_meta[NN + 2]);
        float c = __int_as_float(g_meta[NN + 3]);
        out[0] = a / fmaxf(c, 1.0f);
    }
}

// ---------------- host launcher ----------------------------------------------
extern "C" void kernel_launch(void* const* d_in, const int* in_sizes, int n_in,
                              void* d_out, int out_size) {
    const float* x    = (const float*)d_in[0];
    const int*   row  = (const int*)d_in[1];
    const int*   col  = (const int*)d_in[2];
    const int*   y    = (const int*)d_in[3];
    const void*  mask = d_in[4];
    const float* w1n = (const float*)d_in[5];
    const float* b1n = (const float*)d_in[6];
    const float* w1s = (const float*)d_in[7];
    const float* b1s = (const float*)d_in[8];
    const float* w2n = (const float*)d_in[9];
    const float* b2n = (const float*)d_in[10];
    const float* w2s = (const float*)d_in[11];
    const float* b2s = (const float*)d_in[12];
    float* out = (float*)d_out;

    static int cfg = 0;
    if (!cfg) {
        cudaFuncSetAttribute(k_gemm1, cudaFuncAttributeMaxDynamicSharedMemorySize, G1_SMEM);
        cudaFuncSetAttribute(k_gemm2, cudaFuncAttributeMaxDynamicSharedMemorySize, G2_SMEM);
        cfg = 1;
    }

    void* p_meta;
    cudaGetSymbolAddress(&p_meta, g_meta);
    cudaMemsetAsync(p_meta, 0, (NN + 8) * sizeof(int));

    k_front<<<FB_X + FB_E + FB_W, 256>>>(row, (const unsigned int*)mask, x,
                                         w1n, w1s, w2n, w2s);
    k_scan<<<NB, 256>>>();
    k_fill<<<(EE + 255) / 256, 256>>>(row, col);
    k_agg1<<<(NN * 32 + 511) / 512, 512>>>();
    {
        dim3 grid(HH / 128, (NN + 127) / 128);
        k_gemm1<<<grid, 256, G1_SMEM>>>(b1n, b1s);
    }
    {
        dim3 grid(1, (NN + 127) / 128);
        k_gemm2<<<grid, 256, G2_SMEM>>>();
    }
    k_loss<<<(NN * 32 + 255) / 256, 256>>>(y, mask, b2n, b2s, out);
}

// round 15
// speedup vs baseline: 1.0645x; 1.0039x over previous
#include <cuda_runtime.h>
#include <cuda_bf16.h>
#include <math.h>

#define NN   50000
#define EE   800000
#define DIN  128
#define HH   256
#define CC   47
#define CP   48
#define CPZ  64    // padded bf16 z row (128 B)
#define NB   ((NN + 255) / 256)   // 196 scan blocks

// ---------------- scratch (device globals) -----------------------------------
__device__ __nv_bfloat16 g_xh  [(size_t)NN * DIN];
__device__ __nv_bfloat16 g_aggb[(size_t)NN * DIN];
__device__ __nv_bfloat16 g_h1b [(size_t)NN * HH];
__device__ __nv_bfloat16 g_w1t [256 * HH];           // [n=256][k=256]
__device__ __nv_bfloat16 g_w2t [96 * HH];            // [n=96][k=256]
__device__ __nv_bfloat16 g_zb  [(size_t)NN * CPZ];   // cols 48-63 stay 0
__device__ float g_s   [(size_t)NN * CP];
__device__ int   g_rp  [NN];
__device__ int   g_bsum[256];
__device__ int   g_adj [EE];
__device__ int   g_slot[EE];                         // per-edge slot within its node
// g_meta: [0,NN)=deg, [NN+0]=bytemask, [NN+1]=scan done,
//         [NN+2..3]=loss acc (f32 bits), [NN+4]=loss blocksDone
__device__ int   g_meta[NN + 8];

__device__ __forceinline__ void mma_bf16(float c[4],
        unsigned a0, unsigned a1, unsigned a2, unsigned a3,
        unsigned b0, unsigned b1) {
    asm volatile("mma.sync.aligned.m16n8k16.row.col.f32.bf16.bf16.f32 "
                 "{%0,%1,%2,%3},{%4,%5,%6,%7},{%8,%9},{%0,%1,%2,%3};"
                 : "+f"(c[0]), "+f"(c[1]), "+f"(c[2]), "+f"(c[3])
                 : "r"(a0), "r"(a1), "r"(a2), "r"(a3), "r"(b0), "r"(b1));
}
__device__ __forceinline__ void ldsm4(unsigned &r0, unsigned &r1, unsigned &r2, unsigned &r3,
                                      const void* p) {
    unsigned a = (unsigned)__cvta_generic_to_shared(p);
    asm volatile("ldmatrix.sync.aligned.m8n8.x4.shared.b16 {%0,%1,%2,%3}, [%4];"
                 : "=r"(r0), "=r"(r1), "=r"(r2), "=r"(r3) : "r"(a));
}
__device__ __forceinline__ void ldsm2(unsigned &r0, unsigned &r1, const void* p) {
    unsigned a = (unsigned)__cvta_generic_to_shared(p);
    asm volatile("ldmatrix.sync.aligned.m8n8.x2.shared.b16 {%0,%1}, [%2];"
                 : "=r"(r0), "=r"(r1) : "r"(a));
}
__device__ __forceinline__ void cpa16(void* dst, const void* src, bool p) {
    unsigned d = (unsigned)__cvta_generic_to_shared(dst);
    int sz = p ? 16 : 0;
    asm volatile("cp.async.ca.shared.global [%0], [%1], 16, %2;"
                 :: "r"(d), "l"(src), "r"(sz) : "memory");
}
__device__ __forceinline__ unsigned bf2pack(float lo, float hi) {
    unsigned r;
    asm("cvt.rn.bf16x2.f32 %0, %1, %2;" : "=r"(r) : "f"(hi), "f"(lo));
    return r;
}
// bf16x2 packed add (both halves at once, no unpack)
__device__ __forceinline__ unsigned hadd2(unsigned a, unsigned b) {
    unsigned r;
    asm("add.rn.bf16x2 %0, %1, %2;" : "=r"(r) : "r"(a), "r"(b));
    return r;
}

// ---------------- K1: block-range front (x pack | deg+slot+mask | w pack) ----
#define FB_X 1024
#define FB_E 768
#define FB_W 256
#define PREP_W1 (256 * HH)
#define PREP_W2 (96 * HH)
__global__ void k_front(const int* __restrict__ row,
                        const unsigned int* __restrict__ mw,
                        const float* __restrict__ x,
                        const float* __restrict__ w1n, const float* __restrict__ w1s,
                        const float* __restrict__ w2n, const float* __restrict__ w2s) {
    int b = blockIdx.x, t = threadIdx.x;
    if (b < FB_X) {
        int stride = FB_X * 256;
        const float4* xs = reinterpret_cast<const float4*>(x);
        for (int i = b * 256 + t; i < NN * DIN / 4; i += stride) {
            float4 v = xs[i];
            uint2 r;
            r.x = bf2pack(v.x, v.y);
            r.y = bf2pack(v.z, v.w);
            reinterpret_cast<uint2*>(g_xh)[i] = r;
        }
    } else if (b < FB_X + FB_E) {
        int i0 = (b - FB_X) * 256 + t, stride = FB_E * 256;
        for (int i = i0; i < EE; i += stride)
            g_slot[i] = atomicAdd(&g_meta[row[i]], 1);
        for (int i = i0; i < NN / 4; i += stride)
            if (mw[i] > 1u) g_meta[NN] = 1;
    } else {
        int i0 = (b - FB_X - FB_E) * 256 + t, stride = FB_W * 256;
        for (int i = i0; i < PREP_W1 + PREP_W2; i += stride) {
            if (i < PREP_W1) {
                int n = i >> 8, k = i & 255;
                float v = (k < DIN) ? w1n[k * HH + n] : w1s[(k - DIN) * HH + n];
                g_w1t[i] = __float2bfloat16(v);
            } else {
                int j = i - PREP_W1;
                int n = j >> 8, k = j & 255;
                float v = 0.f;
                if (n < CP) { if (n < CC) v = w2n[k * CC + n]; }
                else        { int n2 = n - CP; if (n2 < CC) v = w2s[k * CC + n2]; }
                g_w2t[j] = __float2bfloat16(v);
            }
        }
    }
}

// ---------------- K2: block scan + last-block finalize -----------------------
__global__ void k_scan() {
    __shared__ int sh[256];
    __shared__ int islast;
    int i = blockIdx.x * 256 + threadIdx.x;
    int v = (i < NN) ? g_meta[i] : 0;
    sh[threadIdx.x] = v;
    __syncthreads();
    for (int o = 1; o < 256; o <<= 1) {
        int t = (threadIdx.x >= o) ? sh[threadIdx.x - o] : 0;
        __syncthreads();
        sh[threadIdx.x] += t;
        __syncthreads();
    }
    int incl = sh[threadIdx.x];
    if (i < NN) g_rp[i] = incl - v;
    if (threadIdx.x == 255) g_bsum[blockIdx.x] = incl;

    __threadfence();
    if (threadIdx.x == 0) {
        int old = atomicAdd(&g_meta[NN + 1], 1);
        islast = (old == gridDim.x - 1);
    }
    __syncthreads();
    if (islast) {
        int b = threadIdx.x;
        int bv = (b < NB) ? g_bsum[b] : 0;
        sh[b] = bv;
        __syncthreads();
        for (int o = 1; o < 256; o <<= 1) {
            int t = (b >= o) ? sh[b - o] : 0;
            __syncthreads();
            sh[b] += t;
            __syncthreads();
        }
        if (b < NB) g_bsum[b] = sh[b] - bv;
    }
}

// ---------------- K3: fill adjacency (atomic-free) ---------------------------
__global__ void k_fill(const int* __restrict__ row, const int* __restrict__ col) {
    int e = blockIdx.x * blockDim.x + threadIdx.x;
    if (e >= EE) return;
    int r = row[e];
    g_adj[g_rp[r] + g_bsum[r >> 8] + g_slot[e]] = col[e];
}

// ---------------- K4: agg1 (warp/node, 2 edges/iter, bf16x2 accumulation) ----
__global__ void k_agg1() {
    int w = (blockIdx.x * blockDim.x + threadIdx.x) >> 5;
    int lane = threadIdx.x & 31;
    if (w >= NN) return;
    int d = g_meta[w];
    int start = g_rp[w] + g_bsum[w >> 8];
    int e = lane >> 4, c = lane & 15;
    unsigned a0 = 0, a1 = 0, a2 = 0, a3 = 0;   // bf16x2 accumulators
    for (int j = 0; j < d; j += 2) {
        int jj = j + e;
        if (jj < d) {
            int s = g_adj[start + jj];
            uint4 v = __ldg(reinterpret_cast<const uint4*>(g_xh + (size_t)s * DIN) + c);
            a0 = hadd2(a0, v.x);
            a1 = hadd2(a1, v.y);
            a2 = hadd2(a2, v.z);
            a3 = hadd2(a3, v.w);
        }
    }
    a0 = hadd2(a0, __shfl_xor_sync(0xffffffffu, a0, 16));
    a1 = hadd2(a1, __shfl_xor_sync(0xffffffffu, a1, 16));
    a2 = hadd2(a2, __shfl_xor_sync(0xffffffffu, a2, 16));
    a3 = hadd2(a3, __shfl_xor_sync(0xffffffffu, a3, 16));
    if (e == 0) {
        float inv = d > 0 ? 1.0f / (float)d : 0.f;
        uint4 r;
        float2 f;
        f = __bfloat1622float2(*reinterpret_cast<__nv_bfloat162*>(&a0));
        r.x = bf2pack(f.x * inv, f.y * inv);
        f = __bfloat1622float2(*reinterpret_cast<__nv_bfloat162*>(&a1));
        r.y = bf2pack(f.x * inv, f.y * inv);
        f = __bfloat1622float2(*reinterpret_cast<__nv_bfloat162*>(&a2));
        r.z = bf2pack(f.x * inv, f.y * inv);
        f = __bfloat1622float2(*reinterpret_cast<__nv_bfloat162*>(&a3));
        r.w = bf2pack(f.x * inv, f.y * inv);
        reinterpret_cast<uint4*>(g_aggb + (size_t)w * DIN)[c] = r;
    }
}

// ---------------- GEMM1 (bf16 mma, 3-stage): h1 = relu([aggb|xh]@w1t^T + b) --
#define G1_SMEM (3*128*72*2 + 3*128*72*2 + 128*4)
__global__ __launch_bounds__(256) void k_gemm1(
        const float* __restrict__ b1n, const float* __restrict__ b1s) {
    extern __shared__ __nv_bfloat16 sm[];
    __nv_bfloat16* As = sm;
    __nv_bfloat16* Bs = sm + 3 * 128 * 72;
    float* sbias = reinterpret_cast<float*>(Bs + 3 * 128 * 72);

    int tid  = threadIdx.x;
    int row0 = blockIdx.y * 128;
    int col0 = blockIdx.x * 128;
    if (tid < 128) sbias[tid] = b1n[col0 + tid] + b1s[col0 + tid];

    int lane = tid & 31, wid = tid >> 5;
    int m_w = (wid & 1) * 64;
    int n_w = (wid >> 1) * 32;

#define AS1(s,m,k) (As + ((s)*128 + (m))*72 + (k))
#define BS1(s,n,k) (Bs + ((s)*128 + (n))*72 + (k))

    auto load_tiles = [&](int s, int kt) {
        #pragma unroll
        for (int i = 0; i < 4; ++i) {
            int idx = tid + i * 256;
            int r = idx >> 3, c = (idx & 7) * 8;
            int gm = row0 + r;
            bool p = gm < NN;
            int gmc = p ? gm : 0;
            const __nv_bfloat16* src = (kt < 2)
                ? g_aggb + (size_t)gmc * DIN + kt * 64 + c
                : g_xh   + (size_t)gmc * DIN + (kt - 2) * 64 + c;
            cpa16(AS1(s, r, c), src, p);
        }
        #pragma unroll
        for (int i = 0; i < 4; ++i) {
            int idx = tid + i * 256;
            int r = idx >> 3, c = (idx & 7) * 8;
            cpa16(BS1(s, r, c), g_w1t + (size_t)(col0 + r) * 256 + kt * 64 + c, true);
        }
    };

    float acc[4][4][4] = {};
    load_tiles(0, 0);
    asm volatile("cp.async.commit_group;" ::: "memory");
    load_tiles(1, 1);
    asm volatile("cp.async.commit_group;" ::: "memory");

    for (int kt = 0; kt < 4; ++kt) {
        if (kt + 2 < 4) load_tiles((kt + 2) % 3, kt + 2);
        asm volatile("cp.async.commit_group;" ::: "memory");
        asm volatile("cp.async.wait_group 2;" ::: "memory");
        __syncthreads();
        int buf = kt % 3;
        #pragma unroll
        for (int ks = 0; ks < 4; ++ks) {
            int kk = ks * 16;
            unsigned af[4][4];
            #pragma unroll
            for (int mt = 0; mt < 4; ++mt) {
                int m = m_w + mt * 16 + (lane & 15);
                int c = kk + (lane >> 4) * 8;
                ldsm4(af[mt][0], af[mt][1], af[mt][2], af[mt][3], AS1(buf, m, c));
            }
            unsigned bf[4][2];
            #pragma unroll
            for (int nt = 0; nt < 4; ++nt) {
                int n = n_w + nt * 8 + (lane & 7);
                int c = kk + ((lane >> 3) & 1) * 8;
                ldsm2(bf[nt][0], bf[nt][1], BS1(buf, n, c));
            }
            #pragma unroll
            for (int mt = 0; mt < 4; ++mt)
                #pragma unroll
                for (int nt = 0; nt < 4; ++nt)
                    mma_bf16(acc[mt][nt], af[mt][0], af[mt][1], af[mt][2], af[mt][3],
                             bf[nt][0], bf[nt][1]);
        }
        __syncthreads();
    }

    int g = lane >> 2, tg = lane & 3;
    #pragma unroll
    for (int mt = 0; mt < 4; ++mt) {
        int mb = row0 + m_w + mt * 16 + g;
        #pragma unroll
        for (int nt = 0; nt < 4; ++nt) {
            int nl = n_w + nt * 8 + 2 * tg;
            int gn = col0 + nl;
            float b0 = sbias[nl], b1 = sbias[nl + 1];
            if (mb < NN) {
                unsigned r = bf2pack(fmaxf(acc[mt][nt][0] + b0, 0.f),
                                     fmaxf(acc[mt][nt][1] + b1, 0.f));
                *reinterpret_cast<unsigned*>(g_h1b + (size_t)mb * HH + gn) = r;
            }
            if (mb + 8 < NN) {
                unsigned r = bf2pack(fmaxf(acc[mt][nt][2] + b0, 0.f),
                                     fmaxf(acc[mt][nt][3] + b1, 0.f));
                *reinterpret_cast<unsigned*>(g_h1b + (size_t)(mb + 8) * HH + gn) = r;
            }
        }
    }
}

// ---------------- GEMM2 (bf16 mma): [z|s] = h1b @ w2t^T ----------------------
#define G2_SMEM (2*128*72*2 + 2*96*72*2)
__global__ __launch_bounds__(256) void k_gemm2() {
    extern __shared__ __nv_bfloat16 sm[];
    __nv_bfloat16* As = sm;
    __nv_bfloat16* Bs = sm + 2 * 128 * 72;

    int tid  = threadIdx.x;
    int row0 = blockIdx.y * 128;
    int lane = tid & 31, wid = tid >> 5;
    int m_w = (wid & 3) * 32;
    int n_w = (wid >> 2) * 48;

#define AS2(s,m,k) (As + ((s)*128 + (m))*72 + (k))
#define BS2(s,n,k) (Bs + ((s)*96 + (n))*72 + (k))

    auto load_tiles = [&](int s, int kt) {
        #pragma unroll
        for (int i = 0; i < 4; ++i) {
            int idx = tid + i * 256;
            int r = idx >> 3, c = (idx & 7) * 8;
            int gm = row0 + r;
            bool p = gm < NN;
            int gmc = p ? gm : 0;
            cpa16(AS2(s, r, c), g_h1b + (size_t)gmc * HH + kt * 64 + c, p);
        }
        #pragma unroll
        for (int i = 0; i < 3; ++i) {
            int idx = tid + i * 256;
            int r = idx >> 3, c = (idx & 7) * 8;
            cpa16(BS2(s, r, c), g_w2t + (size_t)r * 256 + kt * 64 + c, true);
        }
    };

    float acc[2][6][4] = {};
    load_tiles(0, 0);
    asm volatile("cp.async.commit_group;" ::: "memory");

    for (int kt = 0; kt < 4; ++kt) {
        if (kt + 1 < 4) {
            load_tiles((kt + 1) & 1, kt + 1);
            asm volatile("cp.async.commit_group;" ::: "memory");
            asm volatile("cp.async.wait_group 1;" ::: "memory");
        } else {
            asm volatile("cp.async.wait_group 0;" ::: "memory");
        }
        __syncthreads();
        int buf = kt & 1;
        #pragma unroll
        for (int ks = 0; ks < 4; ++ks) {
            int kk = ks * 16;
            unsigned af[2][4];
            #pragma unroll
            for (int mt = 0; mt < 2; ++mt) {
                int m = m_w + mt * 16 + (lane & 15);
                int c = kk + (lane >> 4) * 8;
                ldsm4(af[mt][0], af[mt][1], af[mt][2], af[mt][3], AS2(buf, m, c));
            }
            unsigned bf[6][2];
            #pragma unroll
            for (int nt = 0; nt < 6; ++nt) {
                int n = n_w + nt * 8 + (lane & 7);
                int c = kk + ((lane >> 3) & 1) * 8;
                ldsm2(bf[nt][0], bf[nt][1], BS2(buf, n, c));
            }
            #pragma unroll
            for (int mt = 0; mt < 2; ++mt)
                #pragma unroll
                for (int nt = 0; nt < 6; ++nt)
                    mma_bf16(acc[mt][nt], af[mt][0], af[mt][1], af[mt][2], af[mt][3],
                             bf[nt][0], bf[nt][1]);
        }
        __syncthreads();
    }

    int g = lane >> 2, tg = lane & 3;
    #pragma unroll
    for (int mt = 0; mt < 2; ++mt) {
        int mb = row0 + m_w + mt * 16 + g;
        #pragma unroll
        for (int nt = 0; nt < 6; ++nt) {
            int n = n_w + nt * 8 + 2 * tg;
            if (n < CP) {
                if (mb < NN)
                    *reinterpret_cast<unsigned*>(g_zb + (size_t)mb * CPZ + n) =
                        bf2pack(acc[mt][nt][0], acc[mt][nt][1]);
                if (mb + 8 < NN)
                    *reinterpret_cast<unsigned*>(g_zb + (size_t)(mb + 8) * CPZ + n) =
                        bf2pack(acc[mt][nt][2], acc[mt][nt][3]);
            } else {
                int n2 = n - CP;
                if (mb < NN)
                    *reinterpret_cast<float2*>(g_s + (size_t)mb * CP + n2) =
                        make_float2(acc[mt][nt][0], acc[mt][nt][1]);
                if (mb + 8 < NN)
                    *reinterpret_cast<float2*>(g_s + (size_t)(mb + 8) * CP + n2) =
                        make_float2(acc[mt][nt][2], acc[mt][nt][3]);
            }
        }
    }
}

// ---------------- fused agg2 + loss + finalize (bf16x2 accumulation) ---------
__global__ void k_loss(const int* __restrict__ y,
                       const void* __restrict__ maskp,
                       const float* __restrict__ b2n,
                       const float* __restrict__ b2s,
                       float* __restrict__ out) {
    __shared__ float sz[8][64];
    __shared__ int islast;
    int w = (blockIdx.x * blockDim.x + threadIdx.x) >> 5;
    int lane = threadIdx.x & 31;
    int wl = (threadIdx.x >> 5) & 7;

    if (w < NN) {
        int d = g_meta[w];
        int start = g_rp[w] + g_bsum[w >> 8];
        int e = lane >> 3, c = lane & 7;
        unsigned a0 = 0, a1 = 0, a2 = 0, a3 = 0;   // bf16x2 accumulators
        for (int j = 0; j < d; j += 4) {
            int jj = j + e;
            if (jj < d) {
                int s = g_adj[start + jj];
                uint4 v = __ldg(reinterpret_cast<const uint4*>(g_zb + (size_t)s * CPZ) + c);
                a0 = hadd2(a0, v.x);
                a1 = hadd2(a1, v.y);
                a2 = hadd2(a2, v.z);
                a3 = hadd2(a3, v.w);
            }
        }
        a0 = hadd2(a0, __shfl_xor_sync(0xffffffffu, a0, 8));
        a1 = hadd2(a1, __shfl_xor_sync(0xffffffffu, a1, 8));
        a2 = hadd2(a2, __shfl_xor_sync(0xffffffffu, a2, 8));
        a3 = hadd2(a3, __shfl_xor_sync(0xffffffffu, a3, 8));
        a0 = hadd2(a0, __shfl_xor_sync(0xffffffffu, a0, 16));
        a1 = hadd2(a1, __shfl_xor_sync(0xffffffffu, a1, 16));
        a2 = hadd2(a2, __shfl_xor_sync(0xffffffffu, a2, 16));
        a3 = hadd2(a3, __shfl_xor_sync(0xffffffffu, a3, 16));
        if (e == 0) {
            float inv = d > 0 ? 1.0f / (float)d : 0.f;
            float2 f;
            f = __bfloat1622float2(*reinterpret_cast<__nv_bfloat162*>(&a0));
            sz[wl][c * 8 + 0] = f.x * inv; sz[wl][c * 8 + 1] = f.y * inv;
            f = __bfloat1622float2(*reinterpret_cast<__nv_bfloat162*>(&a1));
            sz[wl][c * 8 + 2] = f.x * inv; sz[wl][c * 8 + 3] = f.y * inv;
            f = __bfloat1622float2(*reinterpret_cast<__nv_bfloat162*>(&a2));
            sz[wl][c * 8 + 4] = f.x * inv; sz[wl][c * 8 + 5] = f.y * inv;
            f = __bfloat1622float2(*reinterpret_cast<__nv_bfloat162*>(&a3));
            sz[wl][c * 8 + 6] = f.x * inv; sz[wl][c * 8 + 7] = f.y * inv;
        }
        __syncwarp();

        const float* ss = g_s + (size_t)w * CP;
        int j2 = lane + 32;
        float l1 = sz[wl][lane] + ss[lane] + b2n[lane] + b2s[lane];
        float l2 = -1e30f;
        if (j2 < CC) l2 = sz[wl][j2] + ss[j2] + b2n[j2] + b2s[j2];

        float m = fmaxf(l1, l2);
        #pragma unroll
        for (int o = 16; o; o >>= 1) m = fmaxf(m, __shfl_xor_sync(0xffffffffu, m, o));
        float se = expf(l1 - m) + ((j2 < CC) ? expf(l2 - m) : 0.f);
        #pragma unroll
        for (int o = 16; o; o >>= 1) se += __shfl_xor_sync(0xffffffffu, se, o);

        if (lane == 0) {
            bool bytemode = (g_meta[NN] != 0);
            bool tm = bytemode ? (((const unsigned char*)maskp)[w] != 0)
                               : (((const int*)maskp)[w] != 0);
            if (tm) {
                int yy = y[w];
                float ly = sz[wl][yy] + ss[yy] + b2n[yy] + b2s[yy];
                float nll = m + logf(se) - ly;
                atomicAdd(reinterpret_cast<float*>(&g_meta[NN + 2]), nll);
                atomicAdd(reinterpret_cast<float*>(&g_meta[NN + 3]), 1.0f);
            }
        }
    }

    __threadfence();
    __syncthreads();
    if (threadIdx.x == 0) {
        int old = atomicAdd(&g_meta[NN + 4], 1);
        islast = (old == gridDim.x - 1);
    }
    __syncthreads();
    if (islast && threadIdx.x == 0) {
        float a = __int_as_float(g_meta[NN + 2]);
        float c = __int_as_float(g_meta[NN + 3]);
        out[0] = a / fmaxf(c, 1.0f);
    }
}

// ---------------- host launcher ----------------------------------------------
extern "C" void kernel_launch(void* const* d_in, const int* in_sizes, int n_in,
                              void* d_out, int out_size) {
    const float* x    = (const float*)d_in[0];
    const int*   row  = (const int*)d_in[1];
    const int*   col  = (const int*)d_in[2];
    const int*   y    = (const int*)d_in[3];
    const void*  mask = d_in[4];
    const float* w1n = (const float*)d_in[5];
    const float* b1n = (const float*)d_in[6];
    const float* w1s = (const float*)d_in[7];
    const float* b1s = (const float*)d_in[8];
    const float* w2n = (const float*)d_in[9];
    const float* b2n = (const float*)d_in[10];
    const float* w2s = (const float*)d_in[11];
    const float* b2s = (const float*)d_in[12];
    float* out = (float*)d_out;

    static int cfg = 0;
    if (!cfg) {
        cudaFuncSetAttribute(k_gemm1, cudaFuncAttributeMaxDynamicSharedMemorySize, G1_SMEM);
        cudaFuncSetAttribute(k_gemm2, cudaFuncAttributeMaxDynamicSharedMemorySize, G2_SMEM);
        cfg = 1;
    }

    void* p_meta;
    cudaGetSymbolAddress(&p_meta, g_meta);
    cudaMemsetAsync(p_meta, 0, (NN + 8) * sizeof(int));

    k_front<<<FB_X + FB_E + FB_W, 256>>>(row, (const unsigned int*)mask, x,
                                         w1n, w1s, w2n, w2s);
    k_scan<<<NB, 256>>>();
    k_fill<<<(EE + 255) / 256, 256>>>(row, col);
    k_agg1<<<(NN * 32 + 511) / 512, 512>>>();
    {
        dim3 grid(HH / 128, (NN + 127) / 128);
        k_gemm1<<<grid, 256, G1_SMEM>>>(b1n, b1s);
    }
    {
        dim3 grid(1, (NN + 127) / 128);
        k_gemm2<<<grid, 256, G2_SMEM>>>();
    }
    k_loss<<<(NN * 32 + 255) / 256, 256>>>(y, mask, b2n, b2s, out);
}

// round 16
// speedup vs baseline: 1.1640x; 1.0936x over previous
#include <cuda_runtime.h>
#include <cuda_bf16.h>
#include <math.h>

#define NN   50000
#define EE   800000
#define DIN  128
#define HH   256
#define CC   47
#define CP   48
#define CPZ  64    // padded bf16 z row (128 B)
#define NB   ((NN + 255) / 256)   // 196 scan blocks

// ---------------- scratch (device globals) -----------------------------------
__device__ __nv_bfloat16 g_xh  [(size_t)NN * DIN];
__device__ __nv_bfloat16 g_aggb[(size_t)NN * DIN];
__device__ __nv_bfloat16 g_w1t [256 * HH];           // [n=256][k=256]
__device__ __nv_bfloat16 g_w2t [96 * HH];            // [n=96][k=256]
__device__ __nv_bfloat16 g_zb  [(size_t)NN * CPZ];   // cols 48-63 stay 0
__device__ float g_s   [(size_t)NN * CP];
__device__ int   g_rp  [NN];
__device__ int   g_bsum[256];
__device__ int   g_adj [EE];
__device__ int   g_slot[EE];                         // per-edge slot within its node
// g_meta: [0,NN)=deg, [NN+0]=bytemask, [NN+1]=scan done,
//         [NN+2..3]=loss acc (f32 bits), [NN+4]=loss blocksDone
__device__ int   g_meta[NN + 8];

__device__ __forceinline__ void mma_bf16(float c[4],
        unsigned a0, unsigned a1, unsigned a2, unsigned a3,
        unsigned b0, unsigned b1) {
    asm volatile("mma.sync.aligned.m16n8k16.row.col.f32.bf16.bf16.f32 "
                 "{%0,%1,%2,%3},{%4,%5,%6,%7},{%8,%9},{%0,%1,%2,%3};"
                 : "+f"(c[0]), "+f"(c[1]), "+f"(c[2]), "+f"(c[3])
                 : "r"(a0), "r"(a1), "r"(a2), "r"(a3), "r"(b0), "r"(b1));
}
__device__ __forceinline__ void ldsm4(unsigned &r0, unsigned &r1, unsigned &r2, unsigned &r3,
                                      const void* p) {
    unsigned a = (unsigned)__cvta_generic_to_shared(p);
    asm volatile("ldmatrix.sync.aligned.m8n8.x4.shared.b16 {%0,%1,%2,%3}, [%4];"
                 : "=r"(r0), "=r"(r1), "=r"(r2), "=r"(r3) : "r"(a));
}
__device__ __forceinline__ void ldsm2(unsigned &r0, unsigned &r1, const void* p) {
    unsigned a = (unsigned)__cvta_generic_to_shared(p);
    asm volatile("ldmatrix.sync.aligned.m8n8.x2.shared.b16 {%0,%1}, [%2];"
                 : "=r"(r0), "=r"(r1) : "r"(a));
}
__device__ __forceinline__ void cpa16(void* dst, const void* src, bool p) {
    unsigned d = (unsigned)__cvta_generic_to_shared(dst);
    int sz = p ? 16 : 0;
    asm volatile("cp.async.ca.shared.global [%0], [%1], 16, %2;"
                 :: "r"(d), "l"(src), "r"(sz) : "memory");
}
__device__ __forceinline__ unsigned bf2pack(float lo, float hi) {
    unsigned r;
    asm("cvt.rn.bf16x2.f32 %0, %1, %2;" : "=r"(r) : "f"(hi), "f"(lo));
    return r;
}
__device__ __forceinline__ unsigned hadd2(unsigned a, unsigned b) {
    unsigned r;
    asm("add.rn.bf16x2 %0, %1, %2;" : "=r"(r) : "r"(a), "r"(b));
    return r;
}

// ---------------- K1: block-range front (x pack | deg+slot+mask | w pack) ----
#define FB_X 1024
#define FB_E 768
#define FB_W 256
#define PREP_W1 (256 * HH)
#define PREP_W2 (96 * HH)
__global__ void k_front(const int* __restrict__ row,
                        const unsigned int* __restrict__ mw,
                        const float* __restrict__ x,
                        const float* __restrict__ w1n, const float* __restrict__ w1s,
                        const float* __restrict__ w2n, const float* __restrict__ w2s) {
    int b = blockIdx.x, t = threadIdx.x;
    if (b < FB_X) {
        int stride = FB_X * 256;
        const float4* xs = reinterpret_cast<const float4*>(x);
        for (int i = b * 256 + t; i < NN * DIN / 4; i += stride) {
            float4 v = xs[i];
            uint2 r;
            r.x = bf2pack(v.x, v.y);
            r.y = bf2pack(v.z, v.w);
            reinterpret_cast<uint2*>(g_xh)[i] = r;
        }
    } else if (b < FB_X + FB_E) {
        int i0 = (b - FB_X) * 256 + t, stride = FB_E * 256;
        for (int i = i0; i < EE; i += stride)
            g_slot[i] = atomicAdd(&g_meta[row[i]], 1);
        for (int i = i0; i < NN / 4; i += stride)
            if (mw[i] > 1u) g_meta[NN] = 1;
    } else {
        int i0 = (b - FB_X - FB_E) * 256 + t, stride = FB_W * 256;
        for (int i = i0; i < PREP_W1 + PREP_W2; i += stride) {
            if (i < PREP_W1) {
                int n = i >> 8, k = i & 255;
                float v = (k < DIN) ? w1n[k * HH + n] : w1s[(k - DIN) * HH + n];
                g_w1t[i] = __float2bfloat16(v);
            } else {
                int j = i - PREP_W1;
                int n = j >> 8, k = j & 255;
                float v = 0.f;
                if (n < CP) { if (n < CC) v = w2n[k * CC + n]; }
                else        { int n2 = n - CP; if (n2 < CC) v = w2s[k * CC + n2]; }
                g_w2t[j] = __float2bfloat16(v);
            }
        }
    }
}

// ---------------- K2: block scan + last-block finalize -----------------------
__global__ void k_scan() {
    __shared__ int sh[256];
    __shared__ int islast;
    int i = blockIdx.x * 256 + threadIdx.x;
    int v = (i < NN) ? g_meta[i] : 0;
    sh[threadIdx.x] = v;
    __syncthreads();
    for (int o = 1; o < 256; o <<= 1) {
        int t = (threadIdx.x >= o) ? sh[threadIdx.x - o] : 0;
        __syncthreads();
        sh[threadIdx.x] += t;
        __syncthreads();
    }
    int incl = sh[threadIdx.x];
    if (i < NN) g_rp[i] = incl - v;
    if (threadIdx.x == 255) g_bsum[blockIdx.x] = incl;

    __threadfence();
    if (threadIdx.x == 0) {
        int old = atomicAdd(&g_meta[NN + 1], 1);
        islast = (old == gridDim.x - 1);
    }
    __syncthreads();
    if (islast) {
        int b = threadIdx.x;
        int bv = (b < NB) ? g_bsum[b] : 0;
        sh[b] = bv;
        __syncthreads();
        for (int o = 1; o < 256; o <<= 1) {
            int t = (b >= o) ? sh[b - o] : 0;
            __syncthreads();
            sh[b] += t;
            __syncthreads();
        }
        if (b < NB) g_bsum[b] = sh[b] - bv;
    }
}

// ---------------- K3: fill adjacency (atomic-free) ---------------------------
__global__ void k_fill(const int* __restrict__ row, const int* __restrict__ col) {
    int e = blockIdx.x * blockDim.x + threadIdx.x;
    if (e >= EE) return;
    int r = row[e];
    g_adj[g_rp[r] + g_bsum[r >> 8] + g_slot[e]] = col[e];
}

// ---------------- K4: agg1 (warp/node, 2 edges/iter, bf16x2 accumulation) ----
__global__ void k_agg1() {
    int w = (blockIdx.x * blockDim.x + threadIdx.x) >> 5;
    int lane = threadIdx.x & 31;
    if (w >= NN) return;
    int d = g_meta[w];
    int start = g_rp[w] + g_bsum[w >> 8];
    int e = lane >> 4, c = lane & 15;
    unsigned a0 = 0, a1 = 0, a2 = 0, a3 = 0;
    for (int j = 0; j < d; j += 2) {
        int jj = j + e;
        if (jj < d) {
            int s = g_adj[start + jj];
            uint4 v = __ldg(reinterpret_cast<const uint4*>(g_xh + (size_t)s * DIN) + c);
            a0 = hadd2(a0, v.x);
            a1 = hadd2(a1, v.y);
            a2 = hadd2(a2, v.z);
            a3 = hadd2(a3, v.w);
        }
    }
    a0 = hadd2(a0, __shfl_xor_sync(0xffffffffu, a0, 16));
    a1 = hadd2(a1, __shfl_xor_sync(0xffffffffu, a1, 16));
    a2 = hadd2(a2, __shfl_xor_sync(0xffffffffu, a2, 16));
    a3 = hadd2(a3, __shfl_xor_sync(0xffffffffu, a3, 16));
    if (e == 0) {
        float inv = d > 0 ? 1.0f / (float)d : 0.f;
        uint4 r;
        float2 f;
        f = __bfloat1622float2(*reinterpret_cast<__nv_bfloat162*>(&a0));
        r.x = bf2pack(f.x * inv, f.y * inv);
        f = __bfloat1622float2(*reinterpret_cast<__nv_bfloat162*>(&a1));
        r.y = bf2pack(f.x * inv, f.y * inv);
        f = __bfloat1622float2(*reinterpret_cast<__nv_bfloat162*>(&a2));
        r.z = bf2pack(f.x * inv, f.y * inv);
        f = __bfloat1622float2(*reinterpret_cast<__nv_bfloat162*>(&a3));
        r.w = bf2pack(f.x * inv, f.y * inv);
        reinterpret_cast<uint4*>(g_aggb + (size_t)w * DIN)[c] = r;
    }
}

// ---------------- FUSED GEMM: h1 tile in smem, then z|s -----------------------
// Block: 128 rows x 256 cols, K=256, 512 threads (16 warps).
// Phase 1: h1 = relu([aggb|xh] @ w1t^T + b) -> smem (bf16, stride 264)
// Phase 2: 8 warps compute [z|s] = h1 @ w2t^T from smem, store to global.
#define GF_A_ST (128 * 72)
#define GF_B_ST (256 * 72)
#define GF_SMEM ((3 * GF_A_ST + 3 * GF_B_ST) * 2 + 256 * 4)
#define H1_STRIDE 264
__global__ __launch_bounds__(512) void k_gemmf(
        const float* __restrict__ b1n, const float* __restrict__ b1s) {
    extern __shared__ __nv_bfloat16 sm[];
    __nv_bfloat16* As = sm;                       // [3][128][72]
    __nv_bfloat16* Bs = sm + 3 * GF_A_ST;         // [3][256][72]
    float* sbias = reinterpret_cast<float*>(sm + 3 * GF_A_ST + 3 * GF_B_ST); // [256]
    __nv_bfloat16* h1s = sm;                      // phase2: [128][264]
    __nv_bfloat16* w2s = sm + 128 * H1_STRIDE;    // phase2: [96][264]

    int tid  = threadIdx.x;
    int row0 = blockIdx.x * 128;
    if (tid < 256) sbias[tid] = b1n[tid] + b1s[tid];

    int lane = tid & 31, wid = tid >> 5;
    int m_w = (wid & 1) * 64;
    int n_w = (wid >> 1) * 32;

#define ASF(s,m,k) (As + ((s)*128 + (m))*72 + (k))
#define BSF(s,n,k) (Bs + ((s)*256 + (n))*72 + (k))

    auto load_tiles = [&](int s, int kt) {
        #pragma unroll
        for (int i = 0; i < 2; ++i) {             // A: 1024 chunks
            int idx = tid + i * 512;
            int r = idx >> 3, c = (idx & 7) * 8;
            int gm = row0 + r;
            bool p = gm < NN;
            int gmc = p ? gm : 0;
            const __nv_bfloat16* src = (kt < 2)
                ? g_aggb + (size_t)gmc * DIN + kt * 64 + c
                : g_xh   + (size_t)gmc * DIN + (kt - 2) * 64 + c;
            cpa16(ASF(s, r, c), src, p);
        }
        #pragma unroll
        for (int i = 0; i < 4; ++i) {             // B: 2048 chunks
            int idx = tid + i * 512;
            int r = idx >> 3, c = (idx & 7) * 8;
            cpa16(BSF(s, r, c), g_w1t + (size_t)r * 256 + kt * 64 + c, true);
        }
    };

    float acc[4][4][4] = {};
    load_tiles(0, 0);
    asm volatile("cp.async.commit_group;" ::: "memory");
    load_tiles(1, 1);
    asm volatile("cp.async.commit_group;" ::: "memory");

    for (int kt = 0; kt < 4; ++kt) {
        if (kt + 2 < 4) load_tiles((kt + 2) % 3, kt + 2);
        asm volatile("cp.async.commit_group;" ::: "memory");
        asm volatile("cp.async.wait_group 2;" ::: "memory");
        __syncthreads();
        int buf = kt % 3;
        #pragma unroll
        for (int ks = 0; ks < 4; ++ks) {
            int kk = ks * 16;
            unsigned af[4][4];
            #pragma unroll
            for (int mt = 0; mt < 4; ++mt) {
                int m = m_w + mt * 16 + (lane & 15);
                int c = kk + (lane >> 4) * 8;
                ldsm4(af[mt][0], af[mt][1], af[mt][2], af[mt][3], ASF(buf, m, c));
            }
            unsigned bf[4][2];
            #pragma unroll
            for (int nt = 0; nt < 4; ++nt) {
                int n = n_w + nt * 8 + (lane & 7);
                int c = kk + ((lane >> 3) & 1) * 8;
                ldsm2(bf[nt][0], bf[nt][1], BSF(buf, n, c));
            }
            #pragma unroll
            for (int mt = 0; mt < 4; ++mt)
                #pragma unroll
                for (int nt = 0; nt < 4; ++nt)
                    mma_bf16(acc[mt][nt], af[mt][0], af[mt][1], af[mt][2], af[mt][3],
                             bf[nt][0], bf[nt][1]);
        }
        __syncthreads();
    }

    // ---- phase 1 -> 2 transition: w2 cp.async + h1 regs -> smem -------------
    {
        #pragma unroll
        for (int i = 0; i < 6; ++i) {             // w2: 96*32 = 3072 chunks
            int idx = tid + i * 512;
            int n = idx >> 5, c = (idx & 31) * 8;
            cpa16(w2s + n * H1_STRIDE + c, g_w2t + (size_t)n * 256 + c, true);
        }
    }
    {
        int g = lane >> 2, tg = lane & 3;
        #pragma unroll
        for (int mt = 0; mt < 4; ++mt) {
            int m0 = m_w + mt * 16 + g;
            #pragma unroll
            for (int nt = 0; nt < 4; ++nt) {
                int n = n_w + nt * 8 + 2 * tg;
                float b0 = sbias[n], b1 = sbias[n + 1];
                *reinterpret_cast<unsigned*>(h1s + m0 * H1_STRIDE + n) =
                    bf2pack(fmaxf(acc[mt][nt][0] + b0, 0.f),
                            fmaxf(acc[mt][nt][1] + b1, 0.f));
                *reinterpret_cast<unsigned*>(h1s + (m0 + 8) * H1_STRIDE + n) =
                    bf2pack(fmaxf(acc[mt][nt][2] + b0, 0.f),
                            fmaxf(acc[mt][nt][3] + b1, 0.f));
            }
        }
    }
    asm volatile("cp.async.commit_group;" ::: "memory");
    asm volatile("cp.async.wait_group 0;" ::: "memory");
    __syncthreads();

    // ---- phase 2: [z|s] = h1 @ w2t^T (warps 0-7; 4m x 2n, warp 32x48) -------
    if (wid < 8) {
        int m_w2 = (wid & 3) * 32;
        int n_w2 = (wid >> 2) * 48;
        float ac2[2][6][4] = {};
        #pragma unroll
        for (int ks = 0; ks < 16; ++ks) {
            int kk = ks * 16;
            unsigned af[2][4];
            #pragma unroll
            for (int mt = 0; mt < 2; ++mt) {
                int m = m_w2 + mt * 16 + (lane & 15);
                int c = kk + (lane >> 4) * 8;
                ldsm4(af[mt][0], af[mt][1], af[mt][2], af[mt][3],
                      h1s + m * H1_STRIDE + c);
            }
            unsigned bf2[6][2];
            #pragma unroll
            for (int nt = 0; nt < 6; ++nt) {
                int n = n_w2 + nt * 8 + (lane & 7);
                int c = kk + ((lane >> 3) & 1) * 8;
                ldsm2(bf2[nt][0], bf2[nt][1], w2s + n * H1_STRIDE + c);
            }
            #pragma unroll
            for (int mt = 0; mt < 2; ++mt)
                #pragma unroll
                for (int nt = 0; nt < 6; ++nt)
                    mma_bf16(ac2[mt][nt], af[mt][0], af[mt][1], af[mt][2], af[mt][3],
                             bf2[nt][0], bf2[nt][1]);
        }

        int g = lane >> 2, tg = lane & 3;
        #pragma unroll
        for (int mt = 0; mt < 2; ++mt) {
            int mb = row0 + m_w2 + mt * 16 + g;
            #pragma unroll
            for (int nt = 0; nt < 6; ++nt) {
                int n = n_w2 + nt * 8 + 2 * tg;
                if (n < CP) {
                    if (mb < NN)
                        *reinterpret_cast<unsigned*>(g_zb + (size_t)mb * CPZ + n) =
                            bf2pack(ac2[mt][nt][0], ac2[mt][nt][1]);
                    if (mb + 8 < NN)
                        *reinterpret_cast<unsigned*>(g_zb + (size_t)(mb + 8) * CPZ + n) =
                            bf2pack(ac2[mt][nt][2], ac2[mt][nt][3]);
                } else {
                    int n2 = n - CP;
                    if (mb < NN)
                        *reinterpret_cast<float2*>(g_s + (size_t)mb * CP + n2) =
                            make_float2(ac2[mt][nt][0], ac2[mt][nt][1]);
                    if (mb + 8 < NN)
                        *reinterpret_cast<float2*>(g_s + (size_t)(mb + 8) * CP + n2) =
                            make_float2(ac2[mt][nt][2], ac2[mt][nt][3]);
                }
            }
        }
    }
}

// ---------------- fused agg2 + loss + finalize + state re-zero ---------------
__global__ void k_loss(const int* __restrict__ y,
                       const void* __restrict__ maskp,
                       const float* __restrict__ b2n,
                       const float* __restrict__ b2s,
                       float* __restrict__ out) {
    __shared__ float sz[8][64];
    __shared__ int islast;
    int w = (blockIdx.x * blockDim.x + threadIdx.x) >> 5;
    int lane = threadIdx.x & 31;
    int wl = (threadIdx.x >> 5) & 7;

    if (w < NN) {
        int d = g_meta[w];
        int start = g_rp[w] + g_bsum[w >> 8];
        int e = lane >> 3, c = lane & 7;
        unsigned a0 = 0, a1 = 0, a2 = 0, a3 = 0;
        for (int j = 0; j < d; j += 4) {
            int jj = j + e;
            if (jj < d) {
                int s = g_adj[start + jj];
                uint4 v = __ldg(reinterpret_cast<const uint4*>(g_zb + (size_t)s * CPZ) + c);
                a0 = hadd2(a0, v.x);
                a1 = hadd2(a1, v.y);
                a2 = hadd2(a2, v.z);
                a3 = hadd2(a3, v.w);
            }
        }
        a0 = hadd2(a0, __shfl_xor_sync(0xffffffffu, a0, 8));
        a1 = hadd2(a1, __shfl_xor_sync(0xffffffffu, a1, 8));
        a2 = hadd2(a2, __shfl_xor_sync(0xffffffffu, a2, 8));
        a3 = hadd2(a3, __shfl_xor_sync(0xffffffffu, a3, 8));
        a0 = hadd2(a0, __shfl_xor_sync(0xffffffffu, a0, 16));
        a1 = hadd2(a1, __shfl_xor_sync(0xffffffffu, a1, 16));
        a2 = hadd2(a2, __shfl_xor_sync(0xffffffffu, a2, 16));
        a3 = hadd2(a3, __shfl_xor_sync(0xffffffffu, a3, 16));
        if (e == 0) {
            float inv = d > 0 ? 1.0f / (float)d : 0.f;
            float2 f;
            f = __bfloat1622float2(*reinterpret_cast<__nv_bfloat162*>(&a0));
            sz[wl][c * 8 + 0] = f.x * inv; sz[wl][c * 8 + 1] = f.y * inv;
            f = __bfloat1622float2(*reinterpret_cast<__nv_bfloat162*>(&a1));
            sz[wl][c * 8 + 2] = f.x * inv; sz[wl][c * 8 + 3] = f.y * inv;
            f = __bfloat1622float2(*reinterpret_cast<__nv_bfloat162*>(&a2));
            sz[wl][c * 8 + 4] = f.x * inv; sz[wl][c * 8 + 5] = f.y * inv;
            f = __bfloat1622float2(*reinterpret_cast<__nv_bfloat162*>(&a3));
            sz[wl][c * 8 + 6] = f.x * inv; sz[wl][c * 8 + 7] = f.y * inv;
        }
        __syncwarp();

        const float* ss = g_s + (size_t)w * CP;
        int j2 = lane + 32;
        float l1 = sz[wl][lane] + ss[lane] + b2n[lane] + b2s[lane];
        float l2 = -1e30f;
        if (j2 < CC) l2 = sz[wl][j2] + ss[j2] + b2n[j2] + b2s[j2];

        float m = fmaxf(l1, l2);
        #pragma unroll
        for (int o = 16; o; o >>= 1) m = fmaxf(m, __shfl_xor_sync(0xffffffffu, m, o));
        float se = expf(l1 - m) + ((j2 < CC) ? expf(l2 - m) : 0.f);
        #pragma unroll
        for (int o = 16; o; o >>= 1) se += __shfl_xor_sync(0xffffffffu, se, o);

        if (lane == 0) {
            bool bytemode = (g_meta[NN] != 0);
            bool tm = bytemode ? (((const unsigned char*)maskp)[w] != 0)
                               : (((const int*)maskp)[w] != 0);
            if (tm) {
                int yy = y[w];
                float ly = sz[wl][yy] + ss[yy] + b2n[yy] + b2s[yy];
                float nll = m + logf(se) - ly;
                atomicAdd(reinterpret_cast<float*>(&g_meta[NN + 2]), nll);
                atomicAdd(reinterpret_cast<float*>(&g_meta[NN + 3]), 1.0f);
            }
            g_meta[w] = 0;       // re-zero deg for the next call
        }
    }

    __threadfence();
    __syncthreads();
    if (threadIdx.x == 0) {
        int old = atomicAdd(&g_meta[NN + 4], 1);
        islast = (old == gridDim.x - 1);
    }
    __syncthreads();
    if (islast && threadIdx.x == 0) {
        float a = __int_as_float(g_meta[NN + 2]);
        float c = __int_as_float(g_meta[NN + 3]);
        out[0] = a / fmaxf(c, 1.0f);
        g_meta[NN]     = 0;      // bytemask
        g_meta[NN + 1] = 0;      // scan done counter
        g_meta[NN + 2] = 0;      // loss sum
        g_meta[NN + 3] = 0;      // loss count
        g_meta[NN + 4] = 0;      // blocksDone
    }
}

// ---------------- host launcher ----------------------------------------------
extern "C" void kernel_launch(void* const* d_in, const int* in_sizes, int n_in,
                              void* d_out, int out_size) {
    const float* x    = (const float*)d_in[0];
    const int*   row  = (const int*)d_in[1];
    const int*   col  = (const int*)d_in[2];
    const int*   y    = (const int*)d_in[3];
    const void*  mask = d_in[4];
    const float* w1n = (const float*)d_in[5];
    const float* b1n = (const float*)d_in[6];
    const float* w1s = (const float*)d_in[7];
    const float* b1s = (const float*)d_in[8];
    const float* w2n = (const float*)d_in[9];
    const float* b2n = (const float*)d_in[10];
    const float* w2s = (const float*)d_in[11];
    const float* b2s = (const float*)d_in[12];
    float* out = (float*)d_out;

    static int cfg = 0;
    if (!cfg) {
        cudaFuncSetAttribute(k_gemmf, cudaFuncAttributeMaxDynamicSharedMemorySize, GF_SMEM);
        cfg = 1;
    }

    k_front<<<FB_X + FB_E + FB_W, 256>>>(row, (const unsigned int*)mask, x,
                                         w1n, w1s, w2n, w2s);
    k_scan<<<NB, 256>>>();
    k_fill<<<(EE + 255) / 256, 256>>>(row, col);
    k_agg1<<<(NN * 32 + 511) / 512, 512>>>();
    k_gemmf<<<(NN + 127) / 128, 512, GF_SMEM>>>(b1n, b1s);
    k_loss<<<(NN * 32 + 255) / 256, 256>>>(y, mask, b2n, b2s, out);
}

// round 17
// speedup vs baseline: 1.1656x; 1.0013x over previous
#include <cuda_runtime.h>
#include <cuda_bf16.h>
#include <math.h>

#define NN   50000
#define EE   800000
#define DIN  128
#define HH   256
#define CC   47
#define CP   48
#define CPZ  64    // padded bf16 z row (128 B)
#define NB   ((NN + 255) / 256)   // 196 scan blocks

// ---------------- scratch (device globals) -----------------------------------
__device__ __nv_bfloat16 g_xh  [(size_t)NN * DIN];
__device__ __nv_bfloat16 g_aggb[(size_t)NN * DIN];
__device__ __nv_bfloat16 g_w1t [256 * HH];           // [n=256][k=256]
__device__ __nv_bfloat16 g_w2t [96 * HH];            // [n=96][k=256]
__device__ __nv_bfloat16 g_zb  [(size_t)NN * CPZ];   // cols 48-63 stay 0
__device__ float g_s   [(size_t)NN * CP];
__device__ int   g_rp  [NN];
__device__ int   g_bsum[256];
__device__ int   g_adj [EE];
__device__ int   g_slot[EE];                         // per-edge slot within its node
// g_meta: [0,NN)=deg, [NN+0]=bytemask, [NN+1]=scan done,
//         [NN+2..3]=loss acc (f32 bits), [NN+4]=loss blocksDone
__device__ int   g_meta[NN + 8];

__device__ __forceinline__ void mma_bf16(float c[4],
        unsigned a0, unsigned a1, unsigned a2, unsigned a3,
        unsigned b0, unsigned b1) {
    asm volatile("mma.sync.aligned.m16n8k16.row.col.f32.bf16.bf16.f32 "
                 "{%0,%1,%2,%3},{%4,%5,%6,%7},{%8,%9},{%0,%1,%2,%3};"
                 : "+f"(c[0]), "+f"(c[1]), "+f"(c[2]), "+f"(c[3])
                 : "r"(a0), "r"(a1), "r"(a2), "r"(a3), "r"(b0), "r"(b1));
}
__device__ __forceinline__ void ldsm4(unsigned &r0, unsigned &r1, unsigned &r2, unsigned &r3,
                                      const void* p) {
    unsigned a = (unsigned)__cvta_generic_to_shared(p);
    asm volatile("ldmatrix.sync.aligned.m8n8.x4.shared.b16 {%0,%1,%2,%3}, [%4];"
                 : "=r"(r0), "=r"(r1), "=r"(r2), "=r"(r3) : "r"(a));
}
__device__ __forceinline__ void ldsm2(unsigned &r0, unsigned &r1, const void* p) {
    unsigned a = (unsigned)__cvta_generic_to_shared(p);
    asm volatile("ldmatrix.sync.aligned.m8n8.x2.shared.b16 {%0,%1}, [%2];"
                 : "=r"(r0), "=r"(r1) : "r"(a));
}
__device__ __forceinline__ void cpa16(void* dst, const void* src, bool p) {
    unsigned d = (unsigned)__cvta_generic_to_shared(dst);
    int sz = p ? 16 : 0;
    asm volatile("cp.async.ca.shared.global [%0], [%1], 16, %2;"
                 :: "r"(d), "l"(src), "r"(sz) : "memory");
}
__device__ __forceinline__ unsigned bf2pack(float lo, float hi) {
    unsigned r;
    asm("cvt.rn.bf16x2.f32 %0, %1, %2;" : "=r"(r) : "f"(hi), "f"(lo));
    return r;
}
__device__ __forceinline__ unsigned hadd2(unsigned a, unsigned b) {
    unsigned r;
    asm("add.rn.bf16x2 %0, %1, %2;" : "=r"(r) : "r"(a), "r"(b));
    return r;
}

// ---------------- K1: block-range front (x pack | deg+slot+mask | w pack) ----
#define FB_X 1024
#define FB_E 768
#define FB_W 256
#define PREP_W1 (256 * HH)
#define PREP_W2 (96 * HH)
__global__ void k_front(const int* __restrict__ row,
                        const unsigned int* __restrict__ mw,
                        const float* __restrict__ x,
                        const float* __restrict__ w1n, const float* __restrict__ w1s,
                        const float* __restrict__ w2n, const float* __restrict__ w2s) {
    int b = blockIdx.x, t = threadIdx.x;
    if (b < FB_X) {
        int stride = FB_X * 256;
        const float4* xs = reinterpret_cast<const float4*>(x);
        for (int i = b * 256 + t; i < NN * DIN / 4; i += stride) {
            float4 v = xs[i];
            uint2 r;
            r.x = bf2pack(v.x, v.y);
            r.y = bf2pack(v.z, v.w);
            reinterpret_cast<uint2*>(g_xh)[i] = r;
        }
    } else if (b < FB_X + FB_E) {
        int i0 = (b - FB_X) * 256 + t, stride = FB_E * 256;
        for (int i = i0; i < EE; i += stride)
            g_slot[i] = atomicAdd(&g_meta[row[i]], 1);
        for (int i = i0; i < NN / 4; i += stride)
            if (mw[i] > 1u) g_meta[NN] = 1;
    } else {
        int i0 = (b - FB_X - FB_E) * 256 + t, stride = FB_W * 256;
        for (int i = i0; i < PREP_W1 + PREP_W2; i += stride) {
            if (i < PREP_W1) {
                int n = i >> 8, k = i & 255;
                float v = (k < DIN) ? w1n[k * HH + n] : w1s[(k - DIN) * HH + n];
                g_w1t[i] = __float2bfloat16(v);
            } else {
                int j = i - PREP_W1;
                int n = j >> 8, k = j & 255;
                float v = 0.f;
                if (n < CP) { if (n < CC) v = w2n[k * CC + n]; }
                else        { int n2 = n - CP; if (n2 < CC) v = w2s[k * CC + n2]; }
                g_w2t[j] = __float2bfloat16(v);
            }
        }
    }
}

// ---------------- K2: block scan + last-block finalize -----------------------
__global__ void k_scan() {
    __shared__ int sh[256];
    __shared__ int islast;
    int i = blockIdx.x * 256 + threadIdx.x;
    int v = (i < NN) ? g_meta[i] : 0;
    sh[threadIdx.x] = v;
    __syncthreads();
    for (int o = 1; o < 256; o <<= 1) {
        int t = (threadIdx.x >= o) ? sh[threadIdx.x - o] : 0;
        __syncthreads();
        sh[threadIdx.x] += t;
        __syncthreads();
    }
    int incl = sh[threadIdx.x];
    if (i < NN) g_rp[i] = incl - v;
    if (threadIdx.x == 255) g_bsum[blockIdx.x] = incl;

    __threadfence();
    if (threadIdx.x == 0) {
        int old = atomicAdd(&g_meta[NN + 1], 1);
        islast = (old == gridDim.x - 1);
    }
    __syncthreads();
    if (islast) {
        int b = threadIdx.x;
        int bv = (b < NB) ? g_bsum[b] : 0;
        sh[b] = bv;
        __syncthreads();
        for (int o = 1; o < 256; o <<= 1) {
            int t = (b >= o) ? sh[b - o] : 0;
            __syncthreads();
            sh[b] += t;
            __syncthreads();
        }
        if (b < NB) g_bsum[b] = sh[b] - bv;
    }
}

// ---------------- K3: fill adjacency (atomic-free) ---------------------------
__global__ void k_fill(const int* __restrict__ row, const int* __restrict__ col) {
    int e = blockIdx.x * blockDim.x + threadIdx.x;
    if (e >= EE) return;
    int r = row[e];
    g_adj[g_rp[r] + g_bsum[r >> 8] + g_slot[e]] = col[e];
}

// ---------------- K4: agg1 (warp/node, 4 edges in flight, bf16x2 accum) ------
__global__ void k_agg1() {
    int w = (blockIdx.x * blockDim.x + threadIdx.x) >> 5;
    int lane = threadIdx.x & 31;
    if (w >= NN) return;
    int d = g_meta[w];
    int start = g_rp[w] + g_bsum[w >> 8];
    int e = lane >> 4, c = lane & 15;
    const uint4 z4 = make_uint4(0, 0, 0, 0);
    unsigned a0 = 0, a1 = 0, a2 = 0, a3 = 0;
    for (int j = 0; j < d; j += 4) {
        int j0 = j + e, j1 = j + 2 + e;
        bool p0 = j0 < d, p1 = j1 < d;
        int s0 = p0 ? g_adj[start + j0] : 0;
        int s1 = p1 ? g_adj[start + j1] : 0;
        uint4 v0 = p0 ? __ldg(reinterpret_cast<const uint4*>(g_xh + (size_t)s0 * DIN) + c) : z4;
        uint4 v1 = p1 ? __ldg(reinterpret_cast<const uint4*>(g_xh + (size_t)s1 * DIN) + c) : z4;
        a0 = hadd2(a0, v0.x); a1 = hadd2(a1, v0.y);
        a2 = hadd2(a2, v0.z); a3 = hadd2(a3, v0.w);
        a0 = hadd2(a0, v1.x); a1 = hadd2(a1, v1.y);
        a2 = hadd2(a2, v1.z); a3 = hadd2(a3, v1.w);
    }
    a0 = hadd2(a0, __shfl_xor_sync(0xffffffffu, a0, 16));
    a1 = hadd2(a1, __shfl_xor_sync(0xffffffffu, a1, 16));
    a2 = hadd2(a2, __shfl_xor_sync(0xffffffffu, a2, 16));
    a3 = hadd2(a3, __shfl_xor_sync(0xffffffffu, a3, 16));
    if (e == 0) {
        float inv = d > 0 ? 1.0f / (float)d : 0.f;
        uint4 r;
        float2 f;
        f = __bfloat1622float2(*reinterpret_cast<__nv_bfloat162*>(&a0));
        r.x = bf2pack(f.x * inv, f.y * inv);
        f = __bfloat1622float2(*reinterpret_cast<__nv_bfloat162*>(&a1));
        r.y = bf2pack(f.x * inv, f.y * inv);
        f = __bfloat1622float2(*reinterpret_cast<__nv_bfloat162*>(&a2));
        r.z = bf2pack(f.x * inv, f.y * inv);
        f = __bfloat1622float2(*reinterpret_cast<__nv_bfloat162*>(&a3));
        r.w = bf2pack(f.x * inv, f.y * inv);
        reinterpret_cast<uint4*>(g_aggb + (size_t)w * DIN)[c] = r;
    }
}

// ---------------- FUSED GEMM: h1 tile in smem, then z|s -----------------------
#define GF_A_ST (128 * 72)
#define GF_B_ST (256 * 72)
#define GF_SMEM ((3 * GF_A_ST + 3 * GF_B_ST) * 2 + 256 * 4)
#define H1_STRIDE 264
__global__ __launch_bounds__(512) void k_gemmf(
        const float* __restrict__ b1n, const float* __restrict__ b1s) {
    extern __shared__ __nv_bfloat16 sm[];
    __nv_bfloat16* As = sm;                       // [3][128][72]
    __nv_bfloat16* Bs = sm + 3 * GF_A_ST;         // [3][256][72]
    float* sbias = reinterpret_cast<float*>(sm + 3 * GF_A_ST + 3 * GF_B_ST); // [256]
    __nv_bfloat16* h1s = sm;                      // phase2: [128][264]
    __nv_bfloat16* w2s = sm + 128 * H1_STRIDE;    // phase2: [96][264]

    int tid  = threadIdx.x;
    int row0 = blockIdx.x * 128;
    if (tid < 256) sbias[tid] = b1n[tid] + b1s[tid];

    int lane = tid & 31, wid = tid >> 5;
    int m_w = (wid & 1) * 64;
    int n_w = (wid >> 1) * 32;

#define ASF(s,m,k) (As + ((s)*128 + (m))*72 + (k))
#define BSF(s,n,k) (Bs + ((s)*256 + (n))*72 + (k))

    auto load_tiles = [&](int s, int kt) {
        #pragma unroll
        for (int i = 0; i < 2; ++i) {
            int idx = tid + i * 512;
            int r = idx >> 3, c = (idx & 7) * 8;
            int gm = row0 + r;
            bool p = gm < NN;
            int gmc = p ? gm : 0;
            const __nv_bfloat16* src = (kt < 2)
                ? g_aggb + (size_t)gmc * DIN + kt * 64 + c
                : g_xh   + (size_t)gmc * DIN + (kt - 2) * 64 + c;
            cpa16(ASF(s, r, c), src, p);
        }
        #pragma unroll
        for (int i = 0; i < 4; ++i) {
            int idx = tid + i * 512;
            int r = idx >> 3, c = (idx & 7) * 8;
            cpa16(BSF(s, r, c), g_w1t + (size_t)r * 256 + kt * 64 + c, true);
        }
    };

    float acc[4][4][4] = {};
    load_tiles(0, 0);
    asm volatile("cp.async.commit_group;" ::: "memory");
    load_tiles(1, 1);
    asm volatile("cp.async.commit_group;" ::: "memory");

    for (int kt = 0; kt < 4; ++kt) {
        if (kt + 2 < 4) load_tiles((kt + 2) % 3, kt + 2);
        asm volatile("cp.async.commit_group;" ::: "memory");
        asm volatile("cp.async.wait_group 2;" ::: "memory");
        __syncthreads();
        int buf = kt % 3;
        #pragma unroll
        for (int ks = 0; ks < 4; ++ks) {
            int kk = ks * 16;
            unsigned af[4][4];
            #pragma unroll
            for (int mt = 0; mt < 4; ++mt) {
                int m = m_w + mt * 16 + (lane & 15);
                int c = kk + (lane >> 4) * 8;
                ldsm4(af[mt][0], af[mt][1], af[mt][2], af[mt][3], ASF(buf, m, c));
            }
            unsigned bf[4][2];
            #pragma unroll
            for (int nt = 0; nt < 4; ++nt) {
                int n = n_w + nt * 8 + (lane & 7);
                int c = kk + ((lane >> 3) & 1) * 8;
                ldsm2(bf[nt][0], bf[nt][1], BSF(buf, n, c));
            }
            #pragma unroll
            for (int mt = 0; mt < 4; ++mt)
                #pragma unroll
                for (int nt = 0; nt < 4; ++nt)
                    mma_bf16(acc[mt][nt], af[mt][0], af[mt][1], af[mt][2], af[mt][3],
                             bf[nt][0], bf[nt][1]);
        }
        __syncthreads();
    }

    // ---- phase 1 -> 2 transition: w2 cp.async + h1 regs -> smem -------------
    {
        #pragma unroll
        for (int i = 0; i < 6; ++i) {
            int idx = tid + i * 512;
            int n = idx >> 5, c = (idx & 31) * 8;
            cpa16(w2s + n * H1_STRIDE + c, g_w2t + (size_t)n * 256 + c, true);
        }
    }
    {
        int g = lane >> 2, tg = lane & 3;
        #pragma unroll
        for (int mt = 0; mt < 4; ++mt) {
            int m0 = m_w + mt * 16 + g;
            #pragma unroll
            for (int nt = 0; nt < 4; ++nt) {
                int n = n_w + nt * 8 + 2 * tg;
                float b0 = sbias[n], b1 = sbias[n + 1];
                *reinterpret_cast<unsigned*>(h1s + m0 * H1_STRIDE + n) =
                    bf2pack(fmaxf(acc[mt][nt][0] + b0, 0.f),
                            fmaxf(acc[mt][nt][1] + b1, 0.f));
                *reinterpret_cast<unsigned*>(h1s + (m0 + 8) * H1_STRIDE + n) =
                    bf2pack(fmaxf(acc[mt][nt][2] + b0, 0.f),
                            fmaxf(acc[mt][nt][3] + b1, 0.f));
            }
        }
    }
    asm volatile("cp.async.commit_group;" ::: "memory");
    asm volatile("cp.async.wait_group 0;" ::: "memory");
    __syncthreads();

    // ---- phase 2: [z|s] = h1 @ w2t^T (warps 0-7; 4m x 2n, warp 32x48) -------
    if (wid < 8) {
        int m_w2 = (wid & 3) * 32;
        int n_w2 = (wid >> 2) * 48;
        float ac2[2][6][4] = {};
        #pragma unroll
        for (int ks = 0; ks < 16; ++ks) {
            int kk = ks * 16;
            unsigned af[2][4];
            #pragma unroll
            for (int mt = 0; mt < 2; ++mt) {
                int m = m_w2 + mt * 16 + (lane & 15);
                int c = kk + (lane >> 4) * 8;
                ldsm4(af[mt][0], af[mt][1], af[mt][2], af[mt][3],
                      h1s + m * H1_STRIDE + c);
            }
            unsigned bf2[6][2];
            #pragma unroll
            for (int nt = 0; nt < 6; ++nt) {
                int n = n_w2 + nt * 8 + (lane & 7);
                int c = kk + ((lane >> 3) & 1) * 8;
                ldsm2(bf2[nt][0], bf2[nt][1], w2s + n * H1_STRIDE + c);
            }
            #pragma unroll
            for (int mt = 0; mt < 2; ++mt)
                #pragma unroll
                for (int nt = 0; nt < 6; ++nt)
                    mma_bf16(ac2[mt][nt], af[mt][0], af[mt][1], af[mt][2], af[mt][3],
                             bf2[nt][0], bf2[nt][1]);
        }

        int g = lane >> 2, tg = lane & 3;
        #pragma unroll
        for (int mt = 0; mt < 2; ++mt) {
            int mb = row0 + m_w2 + mt * 16 + g;
            #pragma unroll
            for (int nt = 0; nt < 6; ++nt) {
                int n = n_w2 + nt * 8 + 2 * tg;
                if (n < CP) {
                    if (mb < NN)
                        *reinterpret_cast<unsigned*>(g_zb + (size_t)mb * CPZ + n) =
                            bf2pack(ac2[mt][nt][0], ac2[mt][nt][1]);
                    if (mb + 8 < NN)
                        *reinterpret_cast<unsigned*>(g_zb + (size_t)(mb + 8) * CPZ + n) =
                            bf2pack(ac2[mt][nt][2], ac2[mt][nt][3]);
                } else {
                    int n2 = n - CP;
                    if (mb < NN)
                        *reinterpret_cast<float2*>(g_s + (size_t)mb * CP + n2) =
                            make_float2(ac2[mt][nt][0], ac2[mt][nt][1]);
                    if (mb + 8 < NN)
                        *reinterpret_cast<float2*>(g_s + (size_t)(mb + 8) * CP + n2) =
                            make_float2(ac2[mt][nt][2], ac2[mt][nt][3]);
                }
            }
        }
    }
}

// ---------------- fused agg2 + loss + finalize + state re-zero ---------------
__global__ void k_loss(const int* __restrict__ y,
                       const void* __restrict__ maskp,
                       const float* __restrict__ b2n,
                       const float* __restrict__ b2s,
                       float* __restrict__ out) {
    __shared__ float sz[8][64];
    __shared__ int islast;
    int w = (blockIdx.x * blockDim.x + threadIdx.x) >> 5;
    int lane = threadIdx.x & 31;
    int wl = (threadIdx.x >> 5) & 7;

    if (w < NN) {
        int d = g_meta[w];
        int start = g_rp[w] + g_bsum[w >> 8];
        int e = lane >> 3, c = lane & 7;
        unsigned a0 = 0, a1 = 0, a2 = 0, a3 = 0;
        for (int j = 0; j < d; j += 4) {
            int jj = j + e;
            if (jj < d) {
                int s = g_adj[start + jj];
                uint4 v = __ldg(reinterpret_cast<const uint4*>(g_zb + (size_t)s * CPZ) + c);
                a0 = hadd2(a0, v.x);
                a1 = hadd2(a1, v.y);
                a2 = hadd2(a2, v.z);
                a3 = hadd2(a3, v.w);
            }
        }
        a0 = hadd2(a0, __shfl_xor_sync(0xffffffffu, a0, 8));
        a1 = hadd2(a1, __shfl_xor_sync(0xffffffffu, a1, 8));
        a2 = hadd2(a2, __shfl_xor_sync(0xffffffffu, a2, 8));
        a3 = hadd2(a3, __shfl_xor_sync(0xffffffffu, a3, 8));
        a0 = hadd2(a0, __shfl_xor_sync(0xffffffffu, a0, 16));
        a1 = hadd2(a1, __shfl_xor_sync(0xffffffffu, a1, 16));
        a2 = hadd2(a2, __shfl_xor_sync(0xffffffffu, a2, 16));
        a3 = hadd2(a3, __shfl_xor_sync(0xffffffffu, a3, 16));
        if (e == 0) {
            float inv = d > 0 ? 1.0f / (float)d : 0.f;
            float2 f;
            f = __bfloat1622float2(*reinterpret_cast<__nv_bfloat162*>(&a0));
            sz[wl][c * 8 + 0] = f.x * inv; sz[wl][c * 8 + 1] = f.y * inv;
            f = __bfloat1622float2(*reinterpret_cast<__nv_bfloat162*>(&a1));
            sz[wl][c * 8 + 2] = f.x * inv; sz[wl][c * 8 + 3] = f.y * inv;
            f = __bfloat1622float2(*reinterpret_cast<__nv_bfloat162*>(&a2));
            sz[wl][c * 8 + 4] = f.x * inv; sz[wl][c * 8 + 5] = f.y * inv;
            f = __bfloat1622float2(*reinterpret_cast<__nv_bfloat162*>(&a3));
            sz[wl][c * 8 + 6] = f.x * inv; sz[wl][c * 8 + 7] = f.y * inv;
        }
        __syncwarp();

        const float* ss = g_s + (size_t)w * CP;
        int j2 = lane + 32;
        float l1 = sz[wl][lane] + ss[lane] + b2n[lane] + b2s[lane];
        float l2 = -1e30f;
        if (j2 < CC) l2 = sz[wl][j2] + ss[j2] + b2n[j2] + b2s[j2];

        float m = fmaxf(l1, l2);
        #pragma unroll
        for (int o = 16; o; o >>= 1) m = fmaxf(m, __shfl_xor_sync(0xffffffffu, m, o));
        float se = expf(l1 - m) + ((j2 < CC) ? expf(l2 - m) : 0.f);
        #pragma unroll
        for (int o = 16; o; o >>= 1) se += __shfl_xor_sync(0xffffffffu, se, o);

        if (lane == 0) {
            bool bytemode = (g_meta[NN] != 0);
            bool tm = bytemode ? (((const unsigned char*)maskp)[w] != 0)
                               : (((const int*)maskp)[w] != 0);
            if (tm) {
                int yy = y[w];
                float ly = sz[wl][yy] + ss[yy] + b2n[yy] + b2s[yy];
                float nll = m + logf(se) - ly;
                atomicAdd(reinterpret_cast<float*>(&g_meta[NN + 2]), nll);
                atomicAdd(reinterpret_cast<float*>(&g_meta[NN + 3]), 1.0f);
            }
            g_meta[w] = 0;       // re-zero deg for the next call
        }
    }

    __threadfence();
    __syncthreads();
    if (threadIdx.x == 0) {
        int old = atomicAdd(&g_meta[NN + 4], 1);
        islast = (old == gridDim.x - 1);
    }
    __syncthreads();
    if (islast && threadIdx.x == 0) {
        float a = __int_as_float(g_meta[NN + 2]);
        float c = __int_as_float(g_meta[NN + 3]);
        out[0] = a / fmaxf(c, 1.0f);
        g_meta[NN]     = 0;      // bytemask
        g_meta[NN + 1] = 0;      // scan done counter
        g_meta[NN + 2] = 0;      // loss sum
        g_meta[NN + 3] = 0;      // loss count
        g_meta[NN + 4] = 0;      // blocksDone
    }
}

// ---------------- host launcher ----------------------------------------------
extern "C" void kernel_launch(void* const* d_in, const int* in_sizes, int n_in,
                              void* d_out, int out_size) {
    const float* x    = (const float*)d_in[0];
    const int*   row  = (const int*)d_in[1];
    const int*   col  = (const int*)d_in[2];
    const int*   y    = (const int*)d_in[3];
    const void*  mask = d_in[4];
    const float* w1n = (const float*)d_in[5];
    const float* b1n = (const float*)d_in[6];
    const float* w1s = (const float*)d_in[7];
    const float* b1s = (const float*)d_in[8];
    const float* w2n = (const float*)d_in[9];
    const float* b2n = (const float*)d_in[10];
    const float* w2s = (const float*)d_in[11];
    const float* b2s = (const float*)d_in[12];
    float* out = (float*)d_out;

    static int cfg = 0;
    if (!cfg) {
        cudaFuncSetAttribute(k_gemmf, cudaFuncAttributeMaxDynamicSharedMemorySize, GF_SMEM);
        cfg = 1;
    }

    k_front<<<FB_X + FB_E + FB_W, 256>>>(row, (const unsigned int*)mask, x,
                                         w1n, w1s, w2n, w2s);
    k_scan<<<NB, 256>>>();
    k_fill<<<(EE + 255) / 256, 256>>>(row, col);
    k_agg1<<<(NN * 32 + 511) / 512, 512>>>();
    k_gemmf<<<(NN + 127) / 128, 512, GF_SMEM>>>(b1n, b1s);
    k_loss<<<(NN * 32 + 255) / 256, 256>>>(y, mask, b2n, b2s, out);
}